// round 1
// baseline (speedup 1.0000x reference)
#include <cuda_runtime.h>
#include <math.h>

// ---------------------------------------------------------------------------
// Problem constants
// ---------------------------------------------------------------------------
#define BATCH 64
#define NPTS  4096

constexpr int S1 = 500, S2 = 250, S3 = 125;
constexpr int M1 = BATCH * S1;   // 32000
constexpr int M2 = BATCH * S2;   // 16000
constexpr int M3 = BATCH * S3;   // 8000

// ---------------------------------------------------------------------------
// Static device scratch (no runtime allocation allowed)
// ---------------------------------------------------------------------------
constexpr size_t OFF_NX1  = 0;                                  // [M1,3]
constexpr size_t OFF_NX2  = OFF_NX1  + (size_t)M1 * 3;          // [M2,3]
constexpr size_t OFF_FCG  = OFF_NX2  + (size_t)M2 * 3;          // [M1,4]
constexpr size_t OFF_H1   = OFF_FCG  + (size_t)M1 * 4;          // [M1,64]
constexpr size_t OFF_L2G  = OFF_H1   + (size_t)M1 * 64;         // [M1,256]
constexpr size_t OFF_CAT1 = OFF_L2G  + (size_t)M1 * 256;        // [M1,259]
constexpr size_t OFF_L4   = OFF_CAT1 + (size_t)M1 * 259;        // [M1,256]
constexpr size_t OFF_L5   = OFF_L4   + (size_t)M1 * 256;        // [M1,384]
constexpr size_t OFF_NF2  = OFF_L5   + (size_t)M1 * 384;        // [M2,384]
constexpr size_t OFF_CAT2 = OFF_NF2  + (size_t)M2 * 384;        // [M2,387]
constexpr size_t OFF_L7   = OFF_CAT2 + (size_t)M2 * 387;        // [M2,384]
constexpr size_t OFF_NF3  = OFF_L7   + (size_t)M2 * 384;        // [M3,384]
constexpr size_t OFF_L8   = OFF_NF3  + (size_t)M3 * 384;        // [M3,512]
constexpr size_t SCRATCH_SZ = OFF_L8 + (size_t)M3 * 512;

__device__ float g_scratch[SCRATCH_SZ];
__device__ int   g_idx[M1 + M2 + M3];
constexpr int IDX1 = 0, IDX2 = M1, IDX3 = M1 + M2;

// ---------------------------------------------------------------------------
// Confidence MLP: conf = sigmoid(relu(x @ cw1 + cb1) @ cw2 + cb2), per point
// ---------------------------------------------------------------------------
__global__ void conf_kernel(const float* __restrict__ x,
                            const float* __restrict__ cw1,
                            const float* __restrict__ cb1,
                            const float* __restrict__ cw2,
                            const float* __restrict__ cb2,
                            float* __restrict__ conf)
{
    int p = blockIdx.x * blockDim.x + threadIdx.x;
    if (p >= BATCH * NPTS) return;
    float x0 = x[3 * p], x1 = x[3 * p + 1], x2 = x[3 * p + 2];
    float acc = 0.f;
#pragma unroll 8
    for (int j = 0; j < 64; j++) {
        float h = cb1[j] + x0 * cw1[j] + x1 * cw1[64 + j] + x2 * cw1[128 + j];
        h = fmaxf(h, 0.f);
        acc += h * cw2[j];
    }
    float z = acc + cb2[0];
    conf[p] = 1.f / (1.f + expf(-z));
}

// ---------------------------------------------------------------------------
// Farthest point sampling: one block per batch. Points + running distances
// live in registers; block argmax with first-occurrence tie-break (matches
// jnp.argmax). Records the incoming `farthest` each step (first index = 0).
// ---------------------------------------------------------------------------
template <int BDIM, int PT>
__global__ void fps_kernel(const float* __restrict__ pts_ext, long long pts_off,
                           int n, int npoint, int idx_off, long long nx_off)
{
    const float* pts = (pts_off >= 0) ? (g_scratch + pts_off) : pts_ext;
    int b = blockIdx.x;
    pts += (size_t)b * n * 3;
    int tid = threadIdx.x;

    float px[PT], py[PT], pz[PT], dist[PT];
#pragma unroll
    for (int i = 0; i < PT; i++) {
        int gi = tid + i * BDIM;
        if (gi < n) {
            px[i] = pts[3 * gi]; py[i] = pts[3 * gi + 1]; pz[i] = pts[3 * gi + 2];
            dist[i] = 1e10f;
        } else {
            px[i] = py[i] = pz[i] = 0.f;
            dist[i] = -1e30f;
        }
    }

    __shared__ float scx, scy, scz;
    __shared__ int   sfar;
    __shared__ float rv[32];
    __shared__ int   ri[32];
    int lane = tid & 31, wid = tid >> 5;

    int far = 0;
    for (int s = 0; s < npoint; s++) {
        if (tid == 0) g_idx[idx_off + b * npoint + s] = far;
        if (tid == (far % BDIM)) {
            int i = far / BDIM;
            scx = px[i]; scy = py[i]; scz = pz[i];
            if (nx_off >= 0) {
                float* o = g_scratch + nx_off + ((size_t)b * npoint + s) * 3;
                o[0] = px[i]; o[1] = py[i]; o[2] = pz[i];
            }
        }
        __syncthreads();
        float cx = scx, cy = scy, cz = scz;

        float best = -1e38f; int bidx = 0x7fffffff;
#pragma unroll
        for (int i = 0; i < PT; i++) {
            int gi = tid + i * BDIM;
            if (gi < n) {
                float dx = px[i] - cx, dy = py[i] - cy, dz = pz[i] - cz;
                float d = dx * dx + dy * dy + dz * dz;
                if (d < dist[i]) dist[i] = d;
                if (dist[i] > best) { best = dist[i]; bidx = gi; }
            }
        }
#pragma unroll
        for (int off = 16; off > 0; off >>= 1) {
            float ov = __shfl_down_sync(0xffffffffu, best, off);
            int   oi = __shfl_down_sync(0xffffffffu, bidx, off);
            if (ov > best || (ov == best && oi < bidx)) { best = ov; bidx = oi; }
        }
        if (lane == 0) { rv[wid] = best; ri[wid] = bidx; }
        __syncthreads();
        if (tid < 32) {
            constexpr int NW = BDIM / 32;
            float v  = (tid < NW) ? rv[tid] : -1e38f;
            int   ix = (tid < NW) ? ri[tid] : 0x7fffffff;
#pragma unroll
            for (int off = 16; off > 0; off >>= 1) {
                float ov = __shfl_down_sync(0xffffffffu, v, off);
                int   oi = __shfl_down_sync(0xffffffffu, ix, off);
                if (ov > v || (ov == v && oi < ix)) { v = ov; ix = oi; }
            }
            if (tid == 0) sfar = ix;
        }
        __syncthreads();
        far = sfar;
    }
}

// ---------------------------------------------------------------------------
// Build gathered fc = [conf, x] for FPS-1 sampled points
// ---------------------------------------------------------------------------
__global__ void build_fcg(const float* __restrict__ x, const float* __restrict__ conf)
{
    int r = blockIdx.x * blockDim.x + threadIdx.x;
    if (r >= M1) return;
    int b = r / S1;
    int idx = g_idx[IDX1 + r];
    size_t pbase = (size_t)b * NPTS + idx;
    float* o = g_scratch + OFF_FCG + (size_t)r * 4;
    o[0] = conf[pbase];
    o[1] = x[pbase * 3];
    o[2] = x[pbase * 3 + 1];
    o[3] = x[pbase * 3 + 2];
}

// ---------------------------------------------------------------------------
// Generic fp32 GEMM:  C[M,N] = (relu)(A[M,K] @ W[K,N] + bias)
// A and C are offsets into g_scratch (arbitrary row strides), W/bias global.
// 64x64 tile per 256-thread block, 4x4 register blocking, TK=16.
// ---------------------------------------------------------------------------
__global__ void gemm_kernel(long long offA, int lda,
                            const float* __restrict__ W,
                            const float* __restrict__ bias,
                            long long offC, int ldc,
                            int M, int N, int K, int do_relu)
{
    __shared__ __align__(16) float As[16][68];
    __shared__ __align__(16) float Ws[16][68];
    const float* A = g_scratch + offA;
    float* C = g_scratch + offC;

    int tid = threadIdx.x;
    int m0 = blockIdx.x * 64;
    int n0 = blockIdx.y * 64;
    int tx = tid & 15, ty = tid >> 4;

    float acc[4][4];
#pragma unroll
    for (int i = 0; i < 4; i++)
#pragma unroll
        for (int j = 0; j < 4; j++) acc[i][j] = 0.f;

    int ar = tid >> 2, ak = (tid & 3) * 4;   // A loader: row ar, k-chunk ak
    int kr = tid >> 4, nb = (tid & 15) * 4;  // W loader: k row kr, n-chunk nb

    for (int k0 = 0; k0 < K; k0 += 16) {
#pragma unroll
        for (int i = 0; i < 4; i++) {
            int k = k0 + ak + i;
            As[ak + i][ar] = (k < K) ? __ldg(&A[(size_t)(m0 + ar) * lda + k]) : 0.f;
        }
        {
            int k = k0 + kr;
#pragma unroll
            for (int j = 0; j < 4; j++)
                Ws[kr][nb + j] = (k < K) ? __ldg(&W[(size_t)k * N + n0 + nb + j]) : 0.f;
        }
        __syncthreads();
#pragma unroll
        for (int kk = 0; kk < 16; kk++) {
            float4 av = *(const float4*)&As[kk][ty * 4];
            float4 wv = *(const float4*)&Ws[kk][tx * 4];
            float a[4] = {av.x, av.y, av.z, av.w};
            float w[4] = {wv.x, wv.y, wv.z, wv.w};
#pragma unroll
            for (int i = 0; i < 4; i++)
#pragma unroll
                for (int j = 0; j < 4; j++) acc[i][j] += a[i] * w[j];
        }
        __syncthreads();
    }

#pragma unroll
    for (int i = 0; i < 4; i++) {
        int m = m0 + ty * 4 + i;
        if (m >= M) continue;
#pragma unroll
        for (int j = 0; j < 4; j++) {
            int n = n0 + tx * 4 + j;
            float v = acc[i][j] + bias[n];
            if (do_relu) v = fmaxf(v, 0.f);
            C[(size_t)m * ldc + n] = v;
        }
    }
}

// ---------------------------------------------------------------------------
// Copy sampled xyz into the first 3 columns of a concat buffer
// ---------------------------------------------------------------------------
__global__ void copy3_kernel(long long src_off, long long dst_off, int ldd, int rows)
{
    int r = blockIdx.x * blockDim.x + threadIdx.x;
    if (r >= rows) return;
    const float* s = g_scratch + src_off + (size_t)r * 3;
    float* d = g_scratch + dst_off + (size_t)r * ldd;
    d[0] = s[0]; d[1] = s[1]; d[2] = s[2];
}

// ---------------------------------------------------------------------------
// Gather 384-wide feature rows at FPS indices
// ---------------------------------------------------------------------------
__global__ void gather384_kernel(long long src_off, int srcS,
                                 long long dst_off, int idx_off, int S, int total)
{
    int e = blockIdx.x * blockDim.x + threadIdx.x;
    if (e >= total) return;
    int r = e / 384, c = e - r * 384;
    int b = r / S;
    int idx = g_idx[idx_off + r];
    g_scratch[dst_off + (size_t)r * 384 + c] =
        g_scratch[src_off + ((size_t)b * srcS + idx) * 384 + c];
}

// ---------------------------------------------------------------------------
// Max-pool l8 over the 125 sampled points per batch
// ---------------------------------------------------------------------------
__global__ void maxpool_kernel(float* __restrict__ out)
{
    int e = blockIdx.x * blockDim.x + threadIdx.x;
    if (e >= BATCH * 512) return;
    int b = e >> 9, c = e & 511;
    const float* base = g_scratch + OFF_L8 + (size_t)b * S3 * 512 + c;
    float m = base[0];
    for (int s = 1; s < S3; s++) m = fmaxf(m, base[(size_t)s * 512]);
    out[e] = m;
}

// ---------------------------------------------------------------------------
// Launch
// ---------------------------------------------------------------------------
extern "C" void kernel_launch(void* const* d_in, const int* in_sizes, int n_in,
                              void* d_out, int out_size)
{
    const float* x    = (const float*)d_in[0];
    const float* cw1  = (const float*)d_in[1];
    const float* cb1  = (const float*)d_in[2];
    const float* cw2  = (const float*)d_in[3];
    const float* cb2  = (const float*)d_in[4];
    const float* w1   = (const float*)d_in[5];
    const float* b1   = (const float*)d_in[6];
    const float* w2   = (const float*)d_in[7];
    const float* b2   = (const float*)d_in[8];
    const float* w3   = (const float*)d_in[9];
    const float* b3   = (const float*)d_in[10];
    const float* w4   = (const float*)d_in[11];
    const float* b4   = (const float*)d_in[12];
    const float* w5   = (const float*)d_in[13];
    const float* b5   = (const float*)d_in[14];
    const float* w6   = (const float*)d_in[15];
    const float* b6   = (const float*)d_in[16];
    const float* pc1w = (const float*)d_in[17];
    const float* pc1b = (const float*)d_in[18];
    const float* pc2w = (const float*)d_in[19];
    const float* pc2b = (const float*)d_in[20];

    float* out  = (float*)d_out;            // (B,512)
    float* conf = out + BATCH * 512;        // (B,N,1)

    // conf for all points (output + gathered later)
    conf_kernel<<<(BATCH * NPTS + 255) / 256, 256>>>(x, cw1, cb1, cw2, cb2, conf);

    // FPS stage 1 on x (500 of 4096), also emits nx1
    fps_kernel<1024, 4><<<BATCH, 1024>>>(x, -1LL, NPTS, S1, IDX1, (long long)OFF_NX1);

    // Per-point MLP only at sampled points: fc -> 64 -> 256
    build_fcg<<<(M1 + 255) / 256, 256>>>(x, conf);
    gemm_kernel<<<dim3(M1 / 64, 1), 256>>>((long long)OFF_FCG, 4, w1, b1,
                                           (long long)OFF_H1, 64, M1, 64, 4, 1);
    gemm_kernel<<<dim3(M1 / 64, 4), 256>>>((long long)OFF_H1, 64, w2, b2,
                                           (long long)OFF_L2G, 256, M1, 256, 64, 1);

    // l3 = nf1 @ pc1w + pc1b (write into cat1[:,3:]); cat1[:,:3] = nx1
    gemm_kernel<<<dim3(M1 / 64, 4), 256>>>((long long)OFF_L2G, 256, pc1w, pc1b,
                                           (long long)(OFF_CAT1 + 3), 259, M1, 256, 256, 0);
    copy3_kernel<<<(M1 + 255) / 256, 256>>>((long long)OFF_NX1, (long long)OFF_CAT1, 259, M1);

    // l4 = relu(cat1 @ w3 + b3), l5 = relu(l4 @ w4 + b4)
    gemm_kernel<<<dim3(M1 / 64, 4), 256>>>((long long)OFF_CAT1, 259, w3, b3,
                                           (long long)OFF_L4, 256, M1, 256, 259, 1);
    gemm_kernel<<<dim3(M1 / 64, 6), 256>>>((long long)OFF_L4, 256, w4, b4,
                                           (long long)OFF_L5, 384, M1, 384, 256, 1);

    // FPS stage 2 on nx1 (250 of 500), emits nx2; gather l5
    fps_kernel<512, 1><<<BATCH, 512>>>(nullptr, (long long)OFF_NX1, S1, S2, IDX2,
                                       (long long)OFF_NX2);
    gather384_kernel<<<(M2 * 384 + 255) / 256, 256>>>((long long)OFF_L5, S1,
                                                      (long long)OFF_NF2, IDX2, S2, M2 * 384);

    // l6 = nf2 @ pc2w + pc2b into cat2[:,3:]; cat2[:,:3] = nx2
    gemm_kernel<<<dim3(M2 / 64, 6), 256>>>((long long)OFF_NF2, 384, pc2w, pc2b,
                                           (long long)(OFF_CAT2 + 3), 387, M2, 384, 384, 0);
    copy3_kernel<<<(M2 + 255) / 256, 256>>>((long long)OFF_NX2, (long long)OFF_CAT2, 387, M2);

    // l7 = relu(cat2 @ w5 + b5)
    gemm_kernel<<<dim3(M2 / 64, 6), 256>>>((long long)OFF_CAT2, 387, w5, b5,
                                           (long long)OFF_L7, 384, M2, 384, 387, 1);

    // FPS stage 3 on nx2 (125 of 250); gather l7
    fps_kernel<256, 1><<<BATCH, 256>>>(nullptr, (long long)OFF_NX2, S2, S3, IDX3, -1LL);
    gather384_kernel<<<(M3 * 384 + 255) / 256, 256>>>((long long)OFF_L7, S2,
                                                      (long long)OFF_NF3, IDX3, S3, M3 * 384);

    // l8 = relu(nf3 @ w6 + b6), then max over points
    gemm_kernel<<<dim3(M3 / 64, 8), 256>>>((long long)OFF_NF3, 384, w6, b6,
                                           (long long)OFF_L8, 512, M3, 512, 384, 1);
    maxpool_kernel<<<(BATCH * 512 + 255) / 256, 256>>>(out);
}

// round 4
// speedup vs baseline: 1.6860x; 1.6860x over previous
#include <cuda_runtime.h>
#include <math.h>
#include <cstdint>

// ---------------------------------------------------------------------------
// Problem constants
// ---------------------------------------------------------------------------
#define BATCH 64
#define NPTS  4096

constexpr int S1 = 500, S2 = 250, S3 = 125;
constexpr int M1 = BATCH * S1;   // 32000
constexpr int M2 = BATCH * S2;   // 16000
constexpr int M3 = BATCH * S3;   // 8000

// ---------------------------------------------------------------------------
// Static device scratch
// ---------------------------------------------------------------------------
constexpr size_t OFF_NX1  = 0;                                  // [M1,3]
constexpr size_t OFF_NX2  = OFF_NX1  + (size_t)M1 * 3;          // [M2,3]
constexpr size_t OFF_FCG  = OFF_NX2  + (size_t)M2 * 3;          // [M1,4]
constexpr size_t OFF_H1   = OFF_FCG  + (size_t)M1 * 4;          // [M1,64]
constexpr size_t OFF_L2G  = OFF_H1   + (size_t)M1 * 64;         // [M1,256]
constexpr size_t OFF_CAT1 = OFF_L2G  + (size_t)M1 * 256;        // [M1,259]
constexpr size_t OFF_L4   = OFF_CAT1 + (size_t)M1 * 259;        // [M1,256]
constexpr size_t OFF_L5   = OFF_L4   + (size_t)M1 * 256;        // [M1,384]
constexpr size_t OFF_NF2  = OFF_L5   + (size_t)M1 * 384;        // [M2,384]
constexpr size_t OFF_CAT2 = OFF_NF2  + (size_t)M2 * 384;        // [M2,387]
constexpr size_t OFF_L7   = OFF_CAT2 + (size_t)M2 * 387;        // [M2,384]
constexpr size_t OFF_NF3  = OFF_L7   + (size_t)M2 * 384;        // [M3,384]
constexpr size_t OFF_L8   = OFF_NF3  + (size_t)M3 * 384;        // [M3,512]
constexpr size_t SCRATCH_SZ = OFF_L8 + (size_t)M3 * 512;

__device__ float g_scratch[SCRATCH_SZ];
__device__ int   g_idx[M1 + M2 + M3];
constexpr int IDX1 = 0, IDX2 = M1, IDX3 = M1 + M2;

// ---------------------------------------------------------------------------
// tf32 helpers
// ---------------------------------------------------------------------------
__device__ __forceinline__ uint32_t to_tf32(float x) {
    uint32_t y;
    asm("cvt.rna.tf32.f32 %0, %1;" : "=r"(y) : "f"(x));
    return y;
}
__device__ __forceinline__ void mma16n8k8(float* c, const uint32_t* a, const uint32_t* b) {
    asm volatile(
        "mma.sync.aligned.m16n8k8.row.col.f32.tf32.tf32.f32 "
        "{%0,%1,%2,%3}, {%4,%5,%6,%7}, {%8,%9}, {%0,%1,%2,%3};"
        : "+f"(c[0]), "+f"(c[1]), "+f"(c[2]), "+f"(c[3])
        : "r"(a[0]), "r"(a[1]), "r"(a[2]), "r"(a[3]), "r"(b[0]), "r"(b[1]));
}

// ---------------------------------------------------------------------------
// Confidence MLP
// ---------------------------------------------------------------------------
__global__ void conf_kernel(const float* __restrict__ x,
                            const float* __restrict__ cw1,
                            const float* __restrict__ cb1,
                            const float* __restrict__ cw2,
                            const float* __restrict__ cb2,
                            float* __restrict__ conf)
{
    int p = blockIdx.x * blockDim.x + threadIdx.x;
    if (p >= BATCH * NPTS) return;
    float x0 = x[3 * p], x1 = x[3 * p + 1], x2 = x[3 * p + 2];
    float acc = 0.f;
#pragma unroll 8
    for (int j = 0; j < 64; j++) {
        float h = cb1[j] + x0 * cw1[j] + x1 * cw1[64 + j] + x2 * cw1[128 + j];
        h = fmaxf(h, 0.f);
        acc += h * cw2[j];
    }
    float z = acc + cb2[0];
    conf[p] = 1.f / (1.f + expf(-z));
}

// ---------------------------------------------------------------------------
// Farthest point sampling (one block per batch; known-good)
// ---------------------------------------------------------------------------
template <int BDIM, int PT>
__global__ void fps_kernel(const float* __restrict__ pts_ext, long long pts_off,
                           int n, int npoint, int idx_off, long long nx_off)
{
    const float* pts = (pts_off >= 0) ? (g_scratch + pts_off) : pts_ext;
    int b = blockIdx.x;
    pts += (size_t)b * n * 3;
    int tid = threadIdx.x;

    float px[PT], py[PT], pz[PT], dist[PT];
#pragma unroll
    for (int i = 0; i < PT; i++) {
        int gi = tid + i * BDIM;
        if (gi < n) {
            px[i] = pts[3 * gi]; py[i] = pts[3 * gi + 1]; pz[i] = pts[3 * gi + 2];
            dist[i] = 1e10f;
        } else {
            px[i] = py[i] = pz[i] = 0.f;
            dist[i] = -1e30f;
        }
    }

    __shared__ float scx, scy, scz;
    __shared__ int   sfar;
    __shared__ float rv[32];
    __shared__ int   ri[32];
    int lane = tid & 31, wid = tid >> 5;

    int far = 0;
    for (int s = 0; s < npoint; s++) {
        if (tid == 0) g_idx[idx_off + b * npoint + s] = far;
        if (tid == (far % BDIM)) {
            int i = far / BDIM;
            scx = px[i]; scy = py[i]; scz = pz[i];
            if (nx_off >= 0) {
                float* o = g_scratch + nx_off + ((size_t)b * npoint + s) * 3;
                o[0] = px[i]; o[1] = py[i]; o[2] = pz[i];
            }
        }
        __syncthreads();
        float cx = scx, cy = scy, cz = scz;

        float best = -1e38f; int bidx = 0x7fffffff;
#pragma unroll
        for (int i = 0; i < PT; i++) {
            int gi = tid + i * BDIM;
            if (gi < n) {
                float dx = px[i] - cx, dy = py[i] - cy, dz = pz[i] - cz;
                float d = dx * dx + dy * dy + dz * dz;
                if (d < dist[i]) dist[i] = d;
                if (dist[i] > best) { best = dist[i]; bidx = gi; }
            }
        }
#pragma unroll
        for (int off = 16; off > 0; off >>= 1) {
            float ov = __shfl_down_sync(0xffffffffu, best, off);
            int   oi = __shfl_down_sync(0xffffffffu, bidx, off);
            if (ov > best || (ov == best && oi < bidx)) { best = ov; bidx = oi; }
        }
        if (lane == 0) { rv[wid] = best; ri[wid] = bidx; }
        __syncthreads();
        if (tid < 32) {
            constexpr int NW = BDIM / 32;
            float v  = (tid < NW) ? rv[tid] : -1e38f;
            int   ix = (tid < NW) ? ri[tid] : 0x7fffffff;
#pragma unroll
            for (int off = 16; off > 0; off >>= 1) {
                float ov = __shfl_down_sync(0xffffffffu, v, off);
                int   oi = __shfl_down_sync(0xffffffffu, ix, off);
                if (ov > v || (ov == v && oi < ix)) { v = ov; ix = oi; }
            }
            if (tid == 0) sfar = ix;
        }
        __syncthreads();
        far = sfar;
    }
}

// ---------------------------------------------------------------------------
// Build gathered fc = [conf, x] for FPS-1 sampled points
// ---------------------------------------------------------------------------
__global__ void build_fcg(const float* __restrict__ x, const float* __restrict__ conf)
{
    int r = blockIdx.x * blockDim.x + threadIdx.x;
    if (r >= M1) return;
    int b = r / S1;
    int idx = g_idx[IDX1 + r];
    size_t pbase = (size_t)b * NPTS + idx;
    float* o = g_scratch + OFF_FCG + (size_t)r * 4;
    o[0] = conf[pbase];
    o[1] = x[pbase * 3];
    o[2] = x[pbase * 3 + 1];
    o[3] = x[pbase * 3 + 2];
}

// ---------------------------------------------------------------------------
// Fused layer-1: h1 = relu(fcg @ w1 + b1)   (K=4, N=64)
// ---------------------------------------------------------------------------
__global__ void layer1_kernel(const float* __restrict__ w1, const float* __restrict__ b1)
{
    int gid = blockIdx.x * blockDim.x + threadIdx.x;
    if (gid >= M1 * 16) return;
    int r = gid >> 4, q = (gid & 15) * 4;
    float4 a = *(const float4*)(g_scratch + OFF_FCG + (size_t)r * 4);
    float o[4];
#pragma unroll
    for (int j = 0; j < 4; j++) {
        float v = b1[q + j];
        v += a.x * __ldg(&w1[0 * 64 + q + j]);
        v += a.y * __ldg(&w1[1 * 64 + q + j]);
        v += a.z * __ldg(&w1[2 * 64 + q + j]);
        v += a.w * __ldg(&w1[3 * 64 + q + j]);
        o[j] = fmaxf(v, 0.f);
    }
    *(float4*)(g_scratch + OFF_H1 + (size_t)r * 64 + q) = make_float4(o[0], o[1], o[2], o[3]);
}

// ---------------------------------------------------------------------------
// tf32 HMMA GEMM: C[M,N](scratch) = relu?(A[M,K](scratch) @ W[K,N](gmem) + bias)
// Block tile 128x128, 256 threads (8 warps, 4m x 2n), warp tile 32x64,
// mma.m16n8k8 tf32, K chunk 32. Smem pad 36 -> conflict-free fragment LDS.
// ---------------------------------------------------------------------------
constexpr int LDA_S = 36;   // bank = (4*row + col) & 31 -> distinct within warp

__global__ void __launch_bounds__(256)
tgemm_kernel(long long offA, int lda,
             const float* __restrict__ W,
             const float* __restrict__ bias,
             long long offC, int ldc,
             int M, int N, int K, int do_relu)
{
    __shared__ uint32_t As[128 * LDA_S];   // [row][k], 18KB
    __shared__ uint32_t Bs[128 * LDA_S];   // [n][k],   18KB

    const float* A = g_scratch + offA;
    float* C = g_scratch + offC;

    int tid = threadIdx.x, lane = tid & 31, wid = tid >> 5;
    int m0 = blockIdx.x * 128, n0 = blockIdx.y * 128;
    int wm = (wid >> 1) * 32;      // warp m offset in tile
    int wn = (wid & 1) * 64;       // warp n offset in tile
    int g = lane >> 2, tg = lane & 3;

    float acc[2][8][4];
#pragma unroll
    for (int i = 0; i < 2; i++)
#pragma unroll
        for (int j = 0; j < 8; j++)
#pragma unroll
            for (int q = 0; q < 4; q++) acc[i][j][q] = 0.f;

    int acol = tid & 31;           // k within chunk
    int arow0 = tid >> 5;          // 0..7
    int bk0 = tid >> 5;            // 0..7
    int bn0 = tid & 31;            // 0..31

    int nch = (K + 31) / 32;
    for (int c = 0; c < nch; c++) {
        int k0 = c * 32;
        // A tile: 128 rows x 32 k, coalesced along k
        {
            bool kok = (k0 + acol) < K;
#pragma unroll
            for (int i = 0; i < 16; i++) {
                int row = arow0 + 8 * i;
                float v = 0.f;
                if (kok && (m0 + row) < M)
                    v = __ldg(&A[(size_t)(m0 + row) * lda + k0 + acol]);
                As[row * LDA_S + acol] = to_tf32(v);
            }
        }
        // B tile: Bs[n][kk] = W[(k0+kk)*N + n0+n], coalesced along n
        {
#pragma unroll
            for (int i = 0; i < 4; i++) {
                int kk = bk0 + 8 * i;
                bool kok = (k0 + kk) < K;
                const float* wrow = W + (size_t)(k0 + kk) * N + n0;
#pragma unroll
                for (int j = 0; j < 4; j++) {
                    int n = bn0 + 32 * j;
                    float v = kok ? __ldg(&wrow[n]) : 0.f;
                    Bs[n * LDA_S + kk] = to_tf32(v);
                }
            }
        }
        __syncthreads();

#pragma unroll
        for (int ks = 0; ks < 4; ks++) {
            int kb = ks * 8;
            uint32_t af[2][4];
#pragma unroll
            for (int mt = 0; mt < 2; mt++) {
                int r = wm + mt * 16 + g;
                af[mt][0] = As[r * LDA_S + kb + tg];
                af[mt][1] = As[(r + 8) * LDA_S + kb + tg];
                af[mt][2] = As[r * LDA_S + kb + tg + 4];
                af[mt][3] = As[(r + 8) * LDA_S + kb + tg + 4];
            }
            uint32_t bf[8][2];
#pragma unroll
            for (int nt = 0; nt < 8; nt++) {
                int n = wn + nt * 8 + g;
                bf[nt][0] = Bs[n * LDA_S + kb + tg];
                bf[nt][1] = Bs[n * LDA_S + kb + tg + 4];
            }
#pragma unroll
            for (int mt = 0; mt < 2; mt++)
#pragma unroll
                for (int nt = 0; nt < 8; nt++)
                    mma16n8k8(acc[mt][nt], af[mt], bf[nt]);
        }
        __syncthreads();
    }

    // Epilogue: bias + relu, direct global stores
#pragma unroll
    for (int mt = 0; mt < 2; mt++) {
        int r0 = m0 + wm + mt * 16 + g;
#pragma unroll
        for (int nt = 0; nt < 8; nt++) {
            int col = n0 + wn + nt * 8 + 2 * tg;
            float bz0 = bias[col], bz1 = bias[col + 1];
            float v0 = acc[mt][nt][0] + bz0, v1 = acc[mt][nt][1] + bz1;
            float v2 = acc[mt][nt][2] + bz0, v3 = acc[mt][nt][3] + bz1;
            if (do_relu) {
                v0 = fmaxf(v0, 0.f); v1 = fmaxf(v1, 0.f);
                v2 = fmaxf(v2, 0.f); v3 = fmaxf(v3, 0.f);
            }
            if (r0 < M) {
                C[(size_t)r0 * ldc + col] = v0;
                C[(size_t)r0 * ldc + col + 1] = v1;
            }
            if (r0 + 8 < M) {
                C[(size_t)(r0 + 8) * ldc + col] = v2;
                C[(size_t)(r0 + 8) * ldc + col + 1] = v3;
            }
        }
    }
}

// ---------------------------------------------------------------------------
// Copy sampled xyz into first 3 columns of a concat buffer
// ---------------------------------------------------------------------------
__global__ void copy3_kernel(long long src_off, long long dst_off, int ldd, int rows)
{
    int r = blockIdx.x * blockDim.x + threadIdx.x;
    if (r >= rows) return;
    const float* s = g_scratch + src_off + (size_t)r * 3;
    float* d = g_scratch + dst_off + (size_t)r * ldd;
    d[0] = s[0]; d[1] = s[1]; d[2] = s[2];
}

// ---------------------------------------------------------------------------
// Gather 384-wide feature rows at FPS indices (float4)
// ---------------------------------------------------------------------------
__global__ void gather384_kernel(long long src_off, int srcS,
                                 long long dst_off, int idx_off, int S, int total4)
{
    int e = blockIdx.x * blockDim.x + threadIdx.x;
    if (e >= total4) return;
    int r = e / 96, c = e - r * 96;
    int b = r / S;
    int idx = g_idx[idx_off + r];
    const float4* s = (const float4*)(g_scratch + src_off);
    float4* d = (float4*)(g_scratch + dst_off);
    d[(size_t)r * 96 + c] = s[((size_t)b * srcS + idx) * 96 + c];
}

// ---------------------------------------------------------------------------
// Max-pool l8 over 125 sampled points per batch
// ---------------------------------------------------------------------------
__global__ void maxpool_kernel(float* __restrict__ out)
{
    int e = blockIdx.x * blockDim.x + threadIdx.x;
    if (e >= BATCH * 512) return;
    int b = e >> 9, c = e & 511;
    const float* base = g_scratch + OFF_L8 + (size_t)b * S3 * 512 + c;
    float m = base[0];
    for (int s = 1; s < S3; s++) m = fmaxf(m, base[(size_t)s * 512]);
    out[e] = m;
}

// ---------------------------------------------------------------------------
// Launch
// ---------------------------------------------------------------------------
extern "C" void kernel_launch(void* const* d_in, const int* in_sizes, int n_in,
                              void* d_out, int out_size)
{
    const float* x    = (const float*)d_in[0];
    const float* cw1  = (const float*)d_in[1];
    const float* cb1  = (const float*)d_in[2];
    const float* cw2  = (const float*)d_in[3];
    const float* cb2  = (const float*)d_in[4];
    const float* w1   = (const float*)d_in[5];
    const float* b1   = (const float*)d_in[6];
    const float* w2   = (const float*)d_in[7];
    const float* b2   = (const float*)d_in[8];
    const float* w3   = (const float*)d_in[9];
    const float* b3   = (const float*)d_in[10];
    const float* w4   = (const float*)d_in[11];
    const float* b4   = (const float*)d_in[12];
    const float* w5   = (const float*)d_in[13];
    const float* b5   = (const float*)d_in[14];
    const float* w6   = (const float*)d_in[15];
    const float* b6   = (const float*)d_in[16];
    const float* pc1w = (const float*)d_in[17];
    const float* pc1b = (const float*)d_in[18];
    const float* pc2w = (const float*)d_in[19];
    const float* pc2b = (const float*)d_in[20];

    float* out  = (float*)d_out;            // (B,512)
    float* conf = out + BATCH * 512;        // (B,N,1)

    conf_kernel<<<(BATCH * NPTS + 255) / 256, 256>>>(x, cw1, cb1, cw2, cb2, conf);
    fps_kernel<1024, 4><<<BATCH, 1024>>>(x, -1LL, NPTS, S1, IDX1, (long long)OFF_NX1);

    build_fcg<<<(M1 + 255) / 256, 256>>>(x, conf);
    layer1_kernel<<<(M1 * 16 + 255) / 256, 256>>>(w1, b1);

    // h1 @ w2 -> l2g   [32000,64]x[64,256]
    tgemm_kernel<<<dim3(M1 / 128, 2), 256>>>(
        (long long)OFF_H1, 64, w2, b2, (long long)OFF_L2G, 256, M1, 256, 64, 1);
    // l2g @ pc1w -> cat1[:,3:]   [32000,256]x[256,256]
    tgemm_kernel<<<dim3(M1 / 128, 2), 256>>>(
        (long long)OFF_L2G, 256, pc1w, pc1b, (long long)(OFF_CAT1 + 3), 259, M1, 256, 256, 0);
    copy3_kernel<<<(M1 + 255) / 256, 256>>>((long long)OFF_NX1, (long long)OFF_CAT1, 259, M1);
    // cat1 @ w3 -> l4   [32000,259]x[259,256]
    tgemm_kernel<<<dim3(M1 / 128, 2), 256>>>(
        (long long)OFF_CAT1, 259, w3, b3, (long long)OFF_L4, 256, M1, 256, 259, 1);
    // l4 @ w4 -> l5   [32000,256]x[256,384]
    tgemm_kernel<<<dim3(M1 / 128, 3), 256>>>(
        (long long)OFF_L4, 256, w4, b4, (long long)OFF_L5, 384, M1, 384, 256, 1);

    fps_kernel<512, 1><<<BATCH, 512>>>(nullptr, (long long)OFF_NX1, S1, S2, IDX2,
                                       (long long)OFF_NX2);
    gather384_kernel<<<(M2 * 96 + 255) / 256, 256>>>((long long)OFF_L5, S1,
                                                     (long long)OFF_NF2, IDX2, S2, M2 * 96);

    // nf2 @ pc2w -> cat2[:,3:]   [16000,384]x[384,384]
    tgemm_kernel<<<dim3(M2 / 128, 3), 256>>>(
        (long long)OFF_NF2, 384, pc2w, pc2b, (long long)(OFF_CAT2 + 3), 387, M2, 384, 384, 0);
    copy3_kernel<<<(M2 + 255) / 256, 256>>>((long long)OFF_NX2, (long long)OFF_CAT2, 387, M2);
    // cat2 @ w5 -> l7   [16000,387]x[387,384]
    tgemm_kernel<<<dim3(M2 / 128, 3), 256>>>(
        (long long)OFF_CAT2, 387, w5, b5, (long long)OFF_L7, 384, M2, 384, 387, 1);

    fps_kernel<256, 1><<<BATCH, 256>>>(nullptr, (long long)OFF_NX2, S2, S3, IDX3, -1LL);
    gather384_kernel<<<(M3 * 96 + 255) / 256, 256>>>((long long)OFF_L7, S2,
                                                     (long long)OFF_NF3, IDX3, S3, M3 * 96);

    // nf3 @ w6 -> l8   [8000,384]x[384,512]  (M edge guarded)
    tgemm_kernel<<<dim3((M3 + 127) / 128, 4), 256>>>(
        (long long)OFF_NF3, 384, w6, b6, (long long)OFF_L8, 512, M3, 512, 384, 1);
    maxpool_kernel<<<(BATCH * 512 + 255) / 256, 256>>>(out);
}

// round 5
// speedup vs baseline: 2.0481x; 1.2148x over previous
#include <cuda_runtime.h>
#include <math.h>
#include <cstdint>

// ---------------------------------------------------------------------------
// Problem constants
// ---------------------------------------------------------------------------
#define BATCH 64
#define NPTS  4096

constexpr int S1 = 500, S2 = 250, S3 = 125;
constexpr int M1 = BATCH * S1;   // 32000
constexpr int M2 = BATCH * S2;   // 16000
constexpr int M3 = BATCH * S3;   // 8000

// ---------------------------------------------------------------------------
// Static device scratch
// ---------------------------------------------------------------------------
constexpr size_t OFF_NX1  = 0;                                  // [M1,3]
constexpr size_t OFF_NX2  = OFF_NX1  + (size_t)M1 * 3;          // [M2,3]
constexpr size_t OFF_FCG  = OFF_NX2  + (size_t)M2 * 3;          // [M1,4]
constexpr size_t OFF_H1   = OFF_FCG  + (size_t)M1 * 4;          // [M1,64]
constexpr size_t OFF_L2G  = OFF_H1   + (size_t)M1 * 64;         // [M1,256]
constexpr size_t OFF_CAT1 = OFF_L2G  + (size_t)M1 * 256;        // [M1,259]
constexpr size_t OFF_L4   = OFF_CAT1 + (size_t)M1 * 259;        // [M1,256]
constexpr size_t OFF_L5   = OFF_L4   + (size_t)M1 * 256;        // [M1,384]
constexpr size_t OFF_NF2  = OFF_L5   + (size_t)M1 * 384;        // [M2,384]
constexpr size_t OFF_CAT2 = OFF_NF2  + (size_t)M2 * 384;        // [M2,387]
constexpr size_t OFF_L7   = OFF_CAT2 + (size_t)M2 * 387;        // [M2,384]
constexpr size_t OFF_NF3  = OFF_L7   + (size_t)M2 * 384;        // [M3,384]
constexpr size_t OFF_L8   = OFF_NF3  + (size_t)M3 * 384;        // [M3,512]
// Preconverted tf32 weights, transposed [N][Kpad], zero-padded in k
constexpr size_t OFF_WC   = OFF_L8 + (size_t)M3 * 512;
constexpr int WC_W2  = 0;        // Kpad  64, N 256
constexpr int WC_PC1 = 16384;    // Kpad 256, N 256
constexpr int WC_W3  = 81920;    // Kpad 288, N 256
constexpr int WC_W4  = 155648;   // Kpad 256, N 384
constexpr int WC_PC2 = 253952;   // Kpad 384, N 384
constexpr int WC_W5  = 401408;   // Kpad 416, N 384
constexpr int WC_W6  = 561152;   // Kpad 384, N 512
constexpr int WC_TOTAL = 757760;
constexpr size_t SCRATCH_SZ = OFF_WC + WC_TOTAL;

__device__ float g_scratch[SCRATCH_SZ];
__device__ int   g_idx[M1 + M2 + M3];
constexpr int IDX1 = 0, IDX2 = M1, IDX3 = M1 + M2;

// ---------------------------------------------------------------------------
// PTX helpers
// ---------------------------------------------------------------------------
__device__ __forceinline__ uint32_t to_tf32(float x) {
    uint32_t y;
    asm("cvt.rna.tf32.f32 %0, %1;" : "=r"(y) : "f"(x));
    return y;
}
__device__ __forceinline__ float round_tf32(float x) {
    return __uint_as_float(to_tf32(x));
}
__device__ __forceinline__ void mma16n8k8(float* c, const uint32_t* a, const uint32_t* b) {
    asm volatile(
        "mma.sync.aligned.m16n8k8.row.col.f32.tf32.tf32.f32 "
        "{%0,%1,%2,%3}, {%4,%5,%6,%7}, {%8,%9}, {%0,%1,%2,%3};"
        : "+f"(c[0]), "+f"(c[1]), "+f"(c[2]), "+f"(c[3])
        : "r"(a[0]), "r"(a[1]), "r"(a[2]), "r"(a[3]), "r"(b[0]), "r"(b[1]));
}
__device__ __forceinline__ uint32_t smem_u32(const void* p) {
    uint32_t a;
    asm("{ .reg .u64 t; cvta.to.shared.u64 t, %1; cvt.u32.u64 %0, t; }"
        : "=r"(a) : "l"(p));
    return a;
}
__device__ __forceinline__ void cpa4(uint32_t dst, const float* src) {
    asm volatile("cp.async.ca.shared.global [%0], [%1], 4;"
                 :: "r"(dst), "l"(src) : "memory");
}
__device__ __forceinline__ void cpa_commit() {
    asm volatile("cp.async.commit_group;" ::: "memory");
}
__device__ __forceinline__ void cpa_wait1() {
    asm volatile("cp.async.wait_group 1;" ::: "memory");
}

// ---------------------------------------------------------------------------
// Confidence MLP
// ---------------------------------------------------------------------------
__global__ void conf_kernel(const float* __restrict__ x,
                            const float* __restrict__ cw1,
                            const float* __restrict__ cb1,
                            const float* __restrict__ cw2,
                            const float* __restrict__ cb2,
                            float* __restrict__ conf)
{
    int p = blockIdx.x * blockDim.x + threadIdx.x;
    if (p >= BATCH * NPTS) return;
    float x0 = x[3 * p], x1 = x[3 * p + 1], x2 = x[3 * p + 2];
    float acc = 0.f;
#pragma unroll 8
    for (int j = 0; j < 64; j++) {
        float h = cb1[j] + x0 * cw1[j] + x1 * cw1[64 + j] + x2 * cw1[128 + j];
        h = fmaxf(h, 0.f);
        acc += h * cw2[j];
    }
    float z = acc + cb2[0];
    conf[p] = 1.f / (1.f + expf(-z));
}

// ---------------------------------------------------------------------------
// Weight preconversion: raw W[K][N] (gmem) -> tf32, transposed, padded
// Wt[n][k] for k < Kpad (zeros for k >= K).
// ---------------------------------------------------------------------------
__global__ void wconv_kernel(const float* __restrict__ w2, const float* __restrict__ pc1w,
                             const float* __restrict__ w3, const float* __restrict__ w4,
                             const float* __restrict__ pc2w, const float* __restrict__ w5,
                             const float* __restrict__ w6)
{
    int e = blockIdx.x * blockDim.x + threadIdx.x;
    if (e >= WC_TOTAL) return;
    const float* src; int base, N, K, Kpad;
    if (e < WC_PC1)      { src = w2;   base = WC_W2;  N = 256; K = 64;  Kpad = 64;  }
    else if (e < WC_W3)  { src = pc1w; base = WC_PC1; N = 256; K = 256; Kpad = 256; }
    else if (e < WC_W4)  { src = w3;   base = WC_W3;  N = 256; K = 259; Kpad = 288; }
    else if (e < WC_PC2) { src = w4;   base = WC_W4;  N = 384; K = 256; Kpad = 256; }
    else if (e < WC_W5)  { src = pc2w; base = WC_PC2; N = 384; K = 384; Kpad = 384; }
    else if (e < WC_W6)  { src = w5;   base = WC_W5;  N = 384; K = 387; Kpad = 416; }
    else                 { src = w6;   base = WC_W6;  N = 512; K = 384; Kpad = 384; }
    int local = e - base;
    int n = local / Kpad, k = local - n * Kpad;
    float v = (k < K) ? __ldg(&src[(size_t)k * N + n]) : 0.f;
    g_scratch[OFF_WC + e] = round_tf32(v);
}

// ---------------------------------------------------------------------------
// Farthest point sampling: one block per batch, ONE barrier per iteration.
// Points live in smem (for centroid lookup) and registers (for updates).
// (dist, ~idx) packed into u64; max-reduce == (max dist, min idx) ==
// jnp.argmax first-occurrence semantics. Per-warp results double-buffered
// by iteration parity so no second barrier is needed.
// ---------------------------------------------------------------------------
template <int BDIM, int PT>
__global__ void fps_kernel(const float* __restrict__ pts_ext, long long pts_off,
                           int n, int npoint, int idx_off, long long nx_off)
{
    extern __shared__ float sh[];
    float* spx = sh;
    float* spy = sh + n;
    float* spz = sh + 2 * n;
    unsigned long long* skey = (unsigned long long*)(sh + 3 * n);  // [2][32]

    const float* pts = (pts_off >= 0) ? (g_scratch + pts_off) : pts_ext;
    int b = blockIdx.x;
    pts += (size_t)b * n * 3;
    int tid = threadIdx.x, lane = tid & 31;
    int wid = tid >> 5;
    constexpr int NW = BDIM / 32;

    float px[PT], py[PT], pz[PT], dist[PT];
    {
        int t = 0;
        for (int i = tid; i < n; i += BDIM, t++) {
            float a = pts[3 * i], bb = pts[3 * i + 1], cc = pts[3 * i + 2];
            spx[i] = a; spy[i] = bb; spz[i] = cc;
            px[t] = a; py[t] = bb; pz[t] = cc; dist[t] = 1e10f;
        }
    }
    __syncthreads();

    int far = 0;
    for (int s = 0; s < npoint; s++) {
        if (tid == 0) {
            g_idx[idx_off + b * npoint + s] = far;
            if (nx_off >= 0) {
                float* o = g_scratch + nx_off + ((size_t)b * npoint + s) * 3;
                o[0] = spx[far]; o[1] = spy[far]; o[2] = spz[far];
            }
        }
        float cx = spx[far], cy = spy[far], cz = spz[far];

        unsigned long long best = 0ull;
#pragma unroll
        for (int t = 0; t < PT; t++) {
            int gi = tid + t * BDIM;
            if (gi < n) {
                float dx = px[t] - cx, dy = py[t] - cy, dz = pz[t] - cz;
                float d = dx * dx + dy * dy + dz * dz;
                if (d < dist[t]) dist[t] = d;
                unsigned long long key =
                    ((unsigned long long)__float_as_uint(dist[t]) << 32) |
                    (unsigned)(~gi);
                if (key > best) best = key;
            }
        }
#pragma unroll
        for (int off = 16; off; off >>= 1) {
            unsigned long long o = __shfl_down_sync(0xffffffffu, best, off);
            if (o > best) best = o;
        }
        int par = s & 1;
        if (lane == 0) skey[par * 32 + wid] = best;
        __syncthreads();
        unsigned long long k2 = (lane < NW) ? skey[par * 32 + lane] : 0ull;
#pragma unroll
        for (int off = 16; off; off >>= 1) {
            unsigned long long o = __shfl_xor_sync(0xffffffffu, k2, off);
            if (o > k2) k2 = o;
        }
        far = (int)(~(unsigned)k2);
    }
}

// ---------------------------------------------------------------------------
// Build gathered fc = [conf, x] for FPS-1 sampled points
// ---------------------------------------------------------------------------
__global__ void build_fcg(const float* __restrict__ x, const float* __restrict__ conf)
{
    int r = blockIdx.x * blockDim.x + threadIdx.x;
    if (r >= M1) return;
    int b = r / S1;
    int idx = g_idx[IDX1 + r];
    size_t pbase = (size_t)b * NPTS + idx;
    float* o = g_scratch + OFF_FCG + (size_t)r * 4;
    o[0] = conf[pbase];
    o[1] = x[pbase * 3];
    o[2] = x[pbase * 3 + 1];
    o[3] = x[pbase * 3 + 2];
}

// ---------------------------------------------------------------------------
// Fused layer-1: h1 = relu(fcg @ w1 + b1)  (K=4, N=64); output tf32-rounded
// ---------------------------------------------------------------------------
__global__ void layer1_kernel(const float* __restrict__ w1, const float* __restrict__ b1)
{
    int gid = blockIdx.x * blockDim.x + threadIdx.x;
    if (gid >= M1 * 16) return;
    int r = gid >> 4, q = (gid & 15) * 4;
    float4 a = *(const float4*)(g_scratch + OFF_FCG + (size_t)r * 4);
    float o[4];
#pragma unroll
    for (int j = 0; j < 4; j++) {
        float v = b1[q + j];
        v += a.x * __ldg(&w1[0 * 64 + q + j]);
        v += a.y * __ldg(&w1[1 * 64 + q + j]);
        v += a.z * __ldg(&w1[2 * 64 + q + j]);
        v += a.w * __ldg(&w1[3 * 64 + q + j]);
        o[j] = round_tf32(fmaxf(v, 0.f));
    }
    *(float4*)(g_scratch + OFF_H1 + (size_t)r * 64 + q) = make_float4(o[0], o[1], o[2], o[3]);
}

// ---------------------------------------------------------------------------
// tf32 HMMA GEMM with cp.async double buffering.
// C[M,N](scratch) = relu?(A[M,Kpad](scratch, tf32-valued) @ Wt + bias)
// Wt: preconverted [N][Kpad] tf32 scratch. Kpad multiple of 32, zero-padded,
// so no k-guards. flags: bit0 = relu, bit1 = round C to tf32.
// Block 128x128, 8 warps (4m x 2n), warp tile 32x64, m16n8k8.
// ---------------------------------------------------------------------------
constexpr int LDA_S = 36;                   // conflict-free fragment LDS
constexpr int TILE_U32 = 128 * LDA_S;       // words per operand buffer
constexpr int TG_SMEM = 4 * TILE_U32 * 4;   // 73728 bytes

__global__ void __launch_bounds__(256)
tgemm_kernel(long long offA, int lda, long long offW, const float* __restrict__ bias,
             long long offC, int ldc, int M, int N, int Kpad, int flags)
{
    extern __shared__ uint32_t sm[];
    const float* A  = g_scratch + offA;
    const float* Wt = g_scratch + offW;
    float* C = g_scratch + offC;

    int tid = threadIdx.x, lane = tid & 31, wid = tid >> 5;
    int m0 = blockIdx.x * 128, n0 = blockIdx.y * 128;
    int wm = (wid >> 1) * 32, wn = (wid & 1) * 64;
    int g = lane >> 2, tg = lane & 3;

    float acc[2][8][4];
#pragma unroll
    for (int i = 0; i < 2; i++)
#pragma unroll
        for (int j = 0; j < 8; j++)
#pragma unroll
            for (int q = 0; q < 4; q++) acc[i][j][q] = 0.f;

    uint32_t sbase = smem_u32(sm);
    int nch = Kpad >> 5;

    // per-thread load roles: row/n = wid + 8i, k = lane (coalesced, no smem
    // store conflicts: consecutive lanes -> consecutive words)
    const float* Arow = A + (size_t)(m0 + wid) * lda + lane;
    const float* Brow = Wt + (size_t)(n0 + wid) * Kpad + lane;

#define TG_ISSUE(c)                                                              \
    do {                                                                         \
        if ((c) < nch) {                                                         \
            uint32_t aw = sbase + (((c) & 1) * 2 * TILE_U32) * 4;                \
            uint32_t bw = aw + TILE_U32 * 4;                                     \
            int k0 = (c) * 32;                                                   \
            _Pragma("unroll")                                                    \
            for (int i = 0; i < 16; i++)                                         \
                cpa4(aw + (((wid + 8 * i) * LDA_S + lane) << 2),                 \
                     Arow + (size_t)(8 * i) * lda + k0);                         \
            _Pragma("unroll")                                                    \
            for (int i = 0; i < 16; i++)                                         \
                cpa4(bw + (((wid + 8 * i) * LDA_S + lane) << 2),                 \
                     Brow + (size_t)(8 * i) * Kpad + k0);                        \
        }                                                                        \
        cpa_commit();                                                            \
    } while (0)

    TG_ISSUE(0);
    TG_ISSUE(1);

    for (int c = 0; c < nch; c++) {
        cpa_wait1();
        __syncthreads();
        uint32_t* As = sm + (c & 1) * 2 * TILE_U32;
        uint32_t* Bs = As + TILE_U32;
#pragma unroll
        for (int ks = 0; ks < 4; ks++) {
            int kb = ks * 8;
            uint32_t af[2][4];
#pragma unroll
            for (int mt = 0; mt < 2; mt++) {
                int r = wm + mt * 16 + g;
                af[mt][0] = As[r * LDA_S + kb + tg];
                af[mt][1] = As[(r + 8) * LDA_S + kb + tg];
                af[mt][2] = As[r * LDA_S + kb + tg + 4];
                af[mt][3] = As[(r + 8) * LDA_S + kb + tg + 4];
            }
            uint32_t bf[8][2];
#pragma unroll
            for (int nt = 0; nt < 8; nt++) {
                int n = wn + nt * 8 + g;
                bf[nt][0] = Bs[n * LDA_S + kb + tg];
                bf[nt][1] = Bs[n * LDA_S + kb + tg + 4];
            }
#pragma unroll
            for (int mt = 0; mt < 2; mt++)
#pragma unroll
                for (int nt = 0; nt < 8; nt++)
                    mma16n8k8(acc[mt][nt], af[mt], bf[nt]);
        }
        __syncthreads();
        TG_ISSUE(c + 2);
    }
#undef TG_ISSUE

    bool do_relu = flags & 1, do_round = flags & 2;
#pragma unroll
    for (int mt = 0; mt < 2; mt++) {
        int r0 = m0 + wm + mt * 16 + g;
#pragma unroll
        for (int nt = 0; nt < 8; nt++) {
            int col = n0 + wn + nt * 8 + 2 * tg;
            float bz0 = bias[col], bz1 = bias[col + 1];
            float v0 = acc[mt][nt][0] + bz0, v1 = acc[mt][nt][1] + bz1;
            float v2 = acc[mt][nt][2] + bz0, v3 = acc[mt][nt][3] + bz1;
            if (do_relu) {
                v0 = fmaxf(v0, 0.f); v1 = fmaxf(v1, 0.f);
                v2 = fmaxf(v2, 0.f); v3 = fmaxf(v3, 0.f);
            }
            if (do_round) {
                v0 = round_tf32(v0); v1 = round_tf32(v1);
                v2 = round_tf32(v2); v3 = round_tf32(v3);
            }
            if (r0 < M) {
                C[(size_t)r0 * ldc + col] = v0;
                C[(size_t)r0 * ldc + col + 1] = v1;
            }
            if (r0 + 8 < M) {
                C[(size_t)(r0 + 8) * ldc + col] = v2;
                C[(size_t)(r0 + 8) * ldc + col + 1] = v3;
            }
        }
    }
}

// ---------------------------------------------------------------------------
// Copy sampled xyz into first 3 columns of a concat buffer (tf32-rounded)
// ---------------------------------------------------------------------------
__global__ void copy3_kernel(long long src_off, long long dst_off, int ldd, int rows)
{
    int r = blockIdx.x * blockDim.x + threadIdx.x;
    if (r >= rows) return;
    const float* s = g_scratch + src_off + (size_t)r * 3;
    float* d = g_scratch + dst_off + (size_t)r * ldd;
    d[0] = round_tf32(s[0]); d[1] = round_tf32(s[1]); d[2] = round_tf32(s[2]);
}

// ---------------------------------------------------------------------------
// Gather 384-wide feature rows at FPS indices (float4)
// ---------------------------------------------------------------------------
__global__ void gather384_kernel(long long src_off, int srcS,
                                 long long dst_off, int idx_off, int S, int total4)
{
    int e = blockIdx.x * blockDim.x + threadIdx.x;
    if (e >= total4) return;
    int r = e / 96, c = e - r * 96;
    int b = r / S;
    int idx = g_idx[idx_off + r];
    const float4* s = (const float4*)(g_scratch + src_off);
    float4* d = (float4*)(g_scratch + dst_off);
    d[(size_t)r * 96 + c] = s[((size_t)b * srcS + idx) * 96 + c];
}

// ---------------------------------------------------------------------------
// Max-pool l8 over 125 sampled points per batch
// ---------------------------------------------------------------------------
__global__ void maxpool_kernel(float* __restrict__ out)
{
    int e = blockIdx.x * blockDim.x + threadIdx.x;
    if (e >= BATCH * 512) return;
    int b = e >> 9, c = e & 511;
    const float* base = g_scratch + OFF_L8 + (size_t)b * S3 * 512 + c;
    float m = base[0];
    for (int s = 1; s < S3; s++) m = fmaxf(m, base[(size_t)s * 512]);
    out[e] = m;
}

// ---------------------------------------------------------------------------
// Launch
// ---------------------------------------------------------------------------
extern "C" void kernel_launch(void* const* d_in, const int* in_sizes, int n_in,
                              void* d_out, int out_size)
{
    const float* x    = (const float*)d_in[0];
    const float* cw1  = (const float*)d_in[1];
    const float* cb1  = (const float*)d_in[2];
    const float* cw2  = (const float*)d_in[3];
    const float* cb2  = (const float*)d_in[4];
    const float* w1   = (const float*)d_in[5];
    const float* b1   = (const float*)d_in[6];
    const float* w2   = (const float*)d_in[7];
    const float* b2   = (const float*)d_in[8];
    const float* w3   = (const float*)d_in[9];
    const float* b3   = (const float*)d_in[10];
    const float* w4   = (const float*)d_in[11];
    const float* b4   = (const float*)d_in[12];
    const float* w5   = (const float*)d_in[13];
    const float* b5   = (const float*)d_in[14];
    const float* w6   = (const float*)d_in[15];
    const float* b6   = (const float*)d_in[16];
    const float* pc1w = (const float*)d_in[17];
    const float* pc1b = (const float*)d_in[18];
    const float* pc2w = (const float*)d_in[19];
    const float* pc2b = (const float*)d_in[20];

    float* out  = (float*)d_out;            // (B,512)
    float* conf = out + BATCH * 512;        // (B,N,1)

    cudaFuncSetAttribute(tgemm_kernel, cudaFuncAttributeMaxDynamicSharedMemorySize,
                         TG_SMEM);
    cudaFuncSetAttribute(fps_kernel<512, 8>, cudaFuncAttributeMaxDynamicSharedMemorySize,
                         3 * NPTS * 4 + 512);

    wconv_kernel<<<(WC_TOTAL + 255) / 256, 256>>>(w2, pc1w, w3, w4, pc2w, w5, w6);
    conf_kernel<<<(BATCH * NPTS + 255) / 256, 256>>>(x, cw1, cb1, cw2, cb2, conf);

    fps_kernel<512, 8><<<BATCH, 512, 3 * NPTS * 4 + 512>>>(
        x, -1LL, NPTS, S1, IDX1, (long long)OFF_NX1);

    build_fcg<<<(M1 + 255) / 256, 256>>>(x, conf);
    layer1_kernel<<<(M1 * 16 + 255) / 256, 256>>>(w1, b1);

    // h1 @ w2 -> l2g   [32000,64]x[64,256]   relu+round
    tgemm_kernel<<<dim3(M1 / 128, 2), 256, TG_SMEM>>>(
        (long long)OFF_H1, 64, (long long)(OFF_WC + WC_W2), b2,
        (long long)OFF_L2G, 256, M1, 256, 64, 3);
    // l2g @ pc1w -> cat1[:,3:]   [32000,256]x[256,256]   round only
    tgemm_kernel<<<dim3(M1 / 128, 2), 256, TG_SMEM>>>(
        (long long)OFF_L2G, 256, (long long)(OFF_WC + WC_PC1), pc1b,
        (long long)(OFF_CAT1 + 3), 259, M1, 256, 256, 2);
    copy3_kernel<<<(M1 + 255) / 256, 256>>>((long long)OFF_NX1, (long long)OFF_CAT1, 259, M1);
    // cat1 @ w3 -> l4   [32000,259(288)]x[.,256]   relu+round
    tgemm_kernel<<<dim3(M1 / 128, 2), 256, TG_SMEM>>>(
        (long long)OFF_CAT1, 259, (long long)(OFF_WC + WC_W3), b3,
        (long long)OFF_L4, 256, M1, 256, 288, 3);
    // l4 @ w4 -> l5   [32000,256]x[256,384]   relu+round
    tgemm_kernel<<<dim3(M1 / 128, 3), 256, TG_SMEM>>>(
        (long long)OFF_L4, 256, (long long)(OFF_WC + WC_W4), b4,
        (long long)OFF_L5, 384, M1, 384, 256, 3);

    fps_kernel<256, 2><<<BATCH, 256, 3 * S1 * 4 + 512>>>(
        nullptr, (long long)OFF_NX1, S1, S2, IDX2, (long long)OFF_NX2);
    gather384_kernel<<<(M2 * 96 + 255) / 256, 256>>>((long long)OFF_L5, S1,
                                                     (long long)OFF_NF2, IDX2, S2, M2 * 96);

    // nf2 @ pc2w -> cat2[:,3:]   [16000,384]x[384,384]   round only
    tgemm_kernel<<<dim3(M2 / 128, 3), 256, TG_SMEM>>>(
        (long long)OFF_NF2, 384, (long long)(OFF_WC + WC_PC2), pc2b,
        (long long)(OFF_CAT2 + 3), 387, M2, 384, 384, 2);
    copy3_kernel<<<(M2 + 255) / 256, 256>>>((long long)OFF_NX2, (long long)OFF_CAT2, 387, M2);
    // cat2 @ w5 -> l7   [16000,387(416)]x[.,384]   relu+round
    tgemm_kernel<<<dim3(M2 / 128, 3), 256, TG_SMEM>>>(
        (long long)OFF_CAT2, 387, (long long)(OFF_WC + WC_W5), b5,
        (long long)OFF_L7, 384, M2, 384, 416, 3);

    fps_kernel<128, 2><<<BATCH, 128, 3 * S2 * 4 + 512>>>(
        nullptr, (long long)OFF_NX2, S2, S3, IDX3, -1LL);
    gather384_kernel<<<(M3 * 96 + 255) / 256, 256>>>((long long)OFF_L7, S2,
                                                     (long long)OFF_NF3, IDX3, S3, M3 * 96);

    // nf3 @ w6 -> l8   [8000,384]x[384,512]   relu, no round (final)
    tgemm_kernel<<<dim3((M3 + 127) / 128, 4), 256, TG_SMEM>>>(
        (long long)OFF_NF3, 384, (long long)(OFF_WC + WC_W6), b6,
        (long long)OFF_L8, 512, M3, 512, 384, 1);
    maxpool_kernel<<<(BATCH * 512 + 255) / 256, 256>>>(out);
}

// round 7
// speedup vs baseline: 2.5382x; 1.2393x over previous
#include <cuda_runtime.h>
#include <cuda_fp16.h>
#include <math.h>
#include <cstdint>

// ---------------------------------------------------------------------------
// Problem constants
// ---------------------------------------------------------------------------
#define BATCH 64
#define NPTS  4096

constexpr int S1 = 500, S2 = 250, S3 = 125;
constexpr int M1 = BATCH * S1;   // 32000
constexpr int M2 = BATCH * S2;   // 16000
constexpr int M3 = BATCH * S3;   // 8000

// ---------------------------------------------------------------------------
// Float scratch (coords, fcg, final l8)
// ---------------------------------------------------------------------------
constexpr size_t OFF_NX1 = 0;                          // [M1,3]
constexpr size_t OFF_NX2 = OFF_NX1 + (size_t)M1 * 3;   // [M2,3]
constexpr size_t OFF_FCG = OFF_NX2 + (size_t)M2 * 3;   // [M1,4]
constexpr size_t OFF_L8  = OFF_FCG + (size_t)M1 * 4;   // [M3,512]
constexpr size_t SCRATCH_SZ = OFF_L8 + (size_t)M3 * 512;

// ---------------------------------------------------------------------------
// Half buffer. Concat buffers are FEATURE-FIRST: cat1 = [l3 | xyz],
// cat2 = [l6 | xyz]; w3/w5 rows are permuted to match in wconv.
// All row strides multiple of 8 halves (16B).
// ---------------------------------------------------------------------------
constexpr size_t HOFF_H1   = 0;                               // [M1,64]
constexpr size_t HOFF_L2G  = HOFF_H1   + (size_t)M1 * 64;     // [M1,256]
constexpr size_t HOFF_CAT1 = HOFF_L2G  + (size_t)M1 * 256;    // [M1,264]: l3 0..255, xyz 256..258
constexpr size_t HOFF_L4   = HOFF_CAT1 + (size_t)M1 * 264;    // [M1,256]
constexpr size_t HOFF_L5   = HOFF_L4   + (size_t)M1 * 256;    // [M1,384]
constexpr size_t HOFF_NF2  = HOFF_L5   + (size_t)M1 * 384;    // [M2,384]
constexpr size_t HOFF_CAT2 = HOFF_NF2  + (size_t)M2 * 384;    // [M2,392]: l6 0..383, xyz 384..386
constexpr size_t HOFF_L7   = HOFF_CAT2 + (size_t)M2 * 392;    // [M2,384]
constexpr size_t HOFF_NF3  = HOFF_L7   + (size_t)M2 * 384;    // [M3,384]
constexpr size_t HOFF_WC   = HOFF_NF3  + (size_t)M3 * 384;
// Preconverted fp16 weights, transposed [N][Kpad], zero-padded in k
constexpr int WC_W2  = 0;        // Kpad  64, N 256
constexpr int WC_PC1 = 16384;    // Kpad 256, N 256
constexpr int WC_W3  = 81920;    // Kpad 288, N 256  (K-permuted)
constexpr int WC_W4  = 155648;   // Kpad 256, N 384
constexpr int WC_PC2 = 253952;   // Kpad 384, N 384
constexpr int WC_W5  = 401408;   // Kpad 416, N 384  (K-permuted)
constexpr int WC_W6  = 561152;   // Kpad 384, N 512
constexpr int WC_TOTAL = 757760;
constexpr size_t HBUF_SZ = HOFF_WC + WC_TOTAL;

__device__ __align__(256) float  g_scratch[SCRATCH_SZ];
__device__ __align__(256) __half g_hbuf[HBUF_SZ];
__device__ int g_idx[M1 + M2 + M3];
constexpr int IDX1 = 0, IDX2 = M1, IDX3 = M1 + M2;

// ---------------------------------------------------------------------------
// PTX helpers
// ---------------------------------------------------------------------------
__device__ __forceinline__ void mma16n8k16(float* c, const uint32_t* a, const uint32_t* b) {
    asm volatile(
        "mma.sync.aligned.m16n8k16.row.col.f32.f16.f16.f32 "
        "{%0,%1,%2,%3}, {%4,%5,%6,%7}, {%8,%9}, {%0,%1,%2,%3};"
        : "+f"(c[0]), "+f"(c[1]), "+f"(c[2]), "+f"(c[3])
        : "r"(a[0]), "r"(a[1]), "r"(a[2]), "r"(a[3]), "r"(b[0]), "r"(b[1]));
}
__device__ __forceinline__ uint32_t smem_u32(const void* p) {
    uint32_t a;
    asm("{ .reg .u64 t; cvta.to.shared.u64 t, %1; cvt.u32.u64 %0, t; }"
        : "=r"(a) : "l"(p));
    return a;
}
__device__ __forceinline__ void cpa16(uint32_t dst, const __half* src) {
    asm volatile("cp.async.ca.shared.global [%0], [%1], 16;"
                 :: "r"(dst), "l"(src) : "memory");
}
__device__ __forceinline__ void cpa_commit() {
    asm volatile("cp.async.commit_group;" ::: "memory");
}
__device__ __forceinline__ void cpa_wait1() {
    asm volatile("cp.async.wait_group 1;" ::: "memory");
}

// ---------------------------------------------------------------------------
// Confidence MLP
// ---------------------------------------------------------------------------
__global__ void conf_kernel(const float* __restrict__ x,
                            const float* __restrict__ cw1,
                            const float* __restrict__ cb1,
                            const float* __restrict__ cw2,
                            const float* __restrict__ cb2,
                            float* __restrict__ conf)
{
    int p = blockIdx.x * blockDim.x + threadIdx.x;
    if (p >= BATCH * NPTS) return;
    float x0 = x[3 * p], x1 = x[3 * p + 1], x2 = x[3 * p + 2];
    float acc = 0.f;
#pragma unroll 8
    for (int j = 0; j < 64; j++) {
        float h = cb1[j] + x0 * cw1[j] + x1 * cw1[64 + j] + x2 * cw1[128 + j];
        h = fmaxf(h, 0.f);
        acc += h * cw2[j];
    }
    float z = acc + cb2[0];
    conf[p] = 1.f / (1.f + expf(-z));
}

// ---------------------------------------------------------------------------
// Weight preconversion: raw W[K][N] -> fp16, transposed [N][Kpad], 0-pad.
// perm3 segments (w3, w5): source row = (k < K-3) ? k+3 : k-(K-3), matching
// feature-first concat layout [feat | xyz].
// ---------------------------------------------------------------------------
__global__ void wconv_kernel(const float* __restrict__ w2, const float* __restrict__ pc1w,
                             const float* __restrict__ w3, const float* __restrict__ w4,
                             const float* __restrict__ pc2w, const float* __restrict__ w5,
                             const float* __restrict__ w6)
{
    int e = blockIdx.x * blockDim.x + threadIdx.x;
    if (e >= WC_TOTAL) return;
    const float* src; int base, N, K, Kpad, perm3;
    if (e < WC_PC1)      { src = w2;   base = WC_W2;  N = 256; K = 64;  Kpad = 64;  perm3 = 0; }
    else if (e < WC_W4)  {
        if (e < WC_W3)   { src = pc1w; base = WC_PC1; N = 256; K = 256; Kpad = 256; perm3 = 0; }
        else             { src = w3;   base = WC_W3;  N = 256; K = 259; Kpad = 288; perm3 = 1; }
    }
    else if (e < WC_PC2) { src = w4;   base = WC_W4;  N = 384; K = 256; Kpad = 256; perm3 = 0; }
    else if (e < WC_W5)  { src = pc2w; base = WC_PC2; N = 384; K = 384; Kpad = 384; perm3 = 0; }
    else if (e < WC_W6)  { src = w5;   base = WC_W5;  N = 384; K = 387; Kpad = 416; perm3 = 1; }
    else                 { src = w6;   base = WC_W6;  N = 512; K = 384; Kpad = 384; perm3 = 0; }
    int local = e - base;
    int n = local / Kpad, k = local - n * Kpad;
    float v = 0.f;
    if (k < K) {
        int ks = perm3 ? ((k < K - 3) ? k + 3 : k - (K - 3)) : k;
        v = __ldg(&src[(size_t)ks * N + n]);
    }
    g_hbuf[HOFF_WC + e] = __float2half_rn(v);
}

// ---------------------------------------------------------------------------
// Farthest point sampling: one block per batch, ONE barrier per iteration.
// (dist, ~idx) packed into u64; max == (max dist, min idx) == jnp.argmax.
// ---------------------------------------------------------------------------
template <int BDIM, int PT>
__global__ void fps_kernel(const float* __restrict__ pts_ext, long long pts_off,
                           int n, int npoint, int idx_off, long long nx_off)
{
    extern __shared__ float sh[];
    float* spx = sh;
    float* spy = sh + n;
    float* spz = sh + 2 * n;
    unsigned long long* skey = (unsigned long long*)(sh + 3 * n + (3 * n & 1));  // [2][32]

    const float* pts = (pts_off >= 0) ? (g_scratch + pts_off) : pts_ext;
    int b = blockIdx.x;
    pts += (size_t)b * n * 3;
    int tid = threadIdx.x, lane = tid & 31;
    int wid = tid >> 5;
    constexpr int NW = BDIM / 32;

    float px[PT], py[PT], pz[PT], dist[PT];
    {
        int t = 0;
        for (int i = tid; i < n; i += BDIM, t++) {
            float a = pts[3 * i], bb = pts[3 * i + 1], cc = pts[3 * i + 2];
            spx[i] = a; spy[i] = bb; spz[i] = cc;
            px[t] = a; py[t] = bb; pz[t] = cc; dist[t] = 1e10f;
        }
    }
    __syncthreads();

    int far = 0;
    for (int s = 0; s < npoint; s++) {
        if (tid == 0) {
            g_idx[idx_off + b * npoint + s] = far;
            if (nx_off >= 0) {
                float* o = g_scratch + nx_off + ((size_t)b * npoint + s) * 3;
                o[0] = spx[far]; o[1] = spy[far]; o[2] = spz[far];
            }
        }
        float cx = spx[far], cy = spy[far], cz = spz[far];

        unsigned long long best = 0ull;
#pragma unroll
        for (int t = 0; t < PT; t++) {
            int gi = tid + t * BDIM;
            if (gi < n) {
                float dx = px[t] - cx, dy = py[t] - cy, dz = pz[t] - cz;
                float d = dx * dx + dy * dy + dz * dz;
                if (d < dist[t]) dist[t] = d;
                unsigned long long key =
                    ((unsigned long long)__float_as_uint(dist[t]) << 32) |
                    (unsigned)(~gi);
                if (key > best) best = key;
            }
        }
#pragma unroll
        for (int off = 16; off; off >>= 1) {
            unsigned long long o = __shfl_down_sync(0xffffffffu, best, off);
            if (o > best) best = o;
        }
        int par = s & 1;
        if (lane == 0) skey[par * 32 + wid] = best;
        __syncthreads();
        unsigned long long k2 = (lane < NW) ? skey[par * 32 + lane] : 0ull;
#pragma unroll
        for (int off = 16; off; off >>= 1) {
            unsigned long long o = __shfl_xor_sync(0xffffffffu, k2, off);
            if (o > k2) k2 = o;
        }
        far = (int)(~(unsigned)k2);
    }
}

// ---------------------------------------------------------------------------
// Build gathered fc = [conf, x] for FPS-1 sampled points
// ---------------------------------------------------------------------------
__global__ void build_fcg(const float* __restrict__ x, const float* __restrict__ conf)
{
    int r = blockIdx.x * blockDim.x + threadIdx.x;
    if (r >= M1) return;
    int b = r / S1;
    int idx = g_idx[IDX1 + r];
    size_t pbase = (size_t)b * NPTS + idx;
    float* o = g_scratch + OFF_FCG + (size_t)r * 4;
    o[0] = conf[pbase];
    o[1] = x[pbase * 3];
    o[2] = x[pbase * 3 + 1];
    o[3] = x[pbase * 3 + 2];
}

// ---------------------------------------------------------------------------
// Fused layer-1: h1 = relu(fcg @ w1 + b1)  (K=4, N=64); output fp16
// ---------------------------------------------------------------------------
__global__ void layer1_kernel(const float* __restrict__ w1, const float* __restrict__ b1)
{
    int gid = blockIdx.x * blockDim.x + threadIdx.x;
    if (gid >= M1 * 16) return;
    int r = gid >> 4, q = (gid & 15) * 4;
    float4 a = *(const float4*)(g_scratch + OFF_FCG + (size_t)r * 4);
    float o[4];
#pragma unroll
    for (int j = 0; j < 4; j++) {
        float v = b1[q + j];
        v += a.x * __ldg(&w1[0 * 64 + q + j]);
        v += a.y * __ldg(&w1[1 * 64 + q + j]);
        v += a.z * __ldg(&w1[2 * 64 + q + j]);
        v += a.w * __ldg(&w1[3 * 64 + q + j]);
        o[j] = fmaxf(v, 0.f);
    }
    __half2 p0 = __floats2half2_rn(o[0], o[1]);
    __half2 p1 = __floats2half2_rn(o[2], o[3]);
    uint2 pk = make_uint2(*(uint32_t*)&p0, *(uint32_t*)&p1);
    *(uint2*)(g_hbuf + HOFF_H1 + (size_t)r * 64 + q) = pk;
}

// ---------------------------------------------------------------------------
// fp16 HMMA GEMM with cp.async double buffering.
// C = relu?(A[M,Kpad](half) @ Wt[N][Kpad](half) + bias), fp32 accumulate.
// flags: bit0 = relu, bit1 = store half into g_hbuf (else fp32 g_scratch).
// Block 128x128, 8 warps (4m x 2n), warp tile 32x64, m16n8k16, K chunk 32.
// ---------------------------------------------------------------------------
constexpr int LDW = 20;                       // words per smem row (16 + pad)
constexpr int TILE_W = 128 * LDW;             // 2560 words
constexpr int TILE_B = TILE_W * 4;            // 10240 bytes
constexpr int TG_SMEM = 4 * TILE_B;           // 40960 bytes

__global__ void __launch_bounds__(256)
tgemm_kernel(long long hoffA, int lda, long long hoffW, const float* __restrict__ bias,
             long long offC, int ldc, int M, int N, int Kpad, int flags)
{
    extern __shared__ uint32_t sm[];
    const __half* Ah = g_hbuf + hoffA;
    const __half* Wh = g_hbuf + hoffW;

    int tid = threadIdx.x, lane = tid & 31, wid = tid >> 5;
    int m0 = blockIdx.x * 128, n0 = blockIdx.y * 128;
    int wm = (wid >> 1) * 32, wn = (wid & 1) * 64;
    int g = lane >> 2, tg = lane & 3;

    float acc[2][8][4];
#pragma unroll
    for (int i = 0; i < 2; i++)
#pragma unroll
        for (int j = 0; j < 8; j++)
#pragma unroll
            for (int q = 0; q < 4; q++) acc[i][j][q] = 0.f;

    uint32_t sbase = smem_u32(sm);
    int nch = Kpad >> 5;

#define TG_ISSUE(c)                                                              \
    do {                                                                         \
        if ((c) < nch) {                                                         \
            uint32_t aw = sbase + ((c) & 1) * 2 * TILE_B;                        \
            uint32_t bw = aw + TILE_B;                                           \
            int k0h = (c) * 32;                                                  \
            _Pragma("unroll")                                                    \
            for (int j = 0; j < 2; j++) {                                        \
                int idx = tid + 256 * j;                                         \
                int row = idx >> 2, cw = idx & 3;                                \
                cpa16(aw + ((row * LDW + cw * 4) << 2),                          \
                      Ah + (size_t)(m0 + row) * lda + k0h + cw * 8);             \
                cpa16(bw + ((row * LDW + cw * 4) << 2),                          \
                      Wh + (size_t)(n0 + row) * Kpad + k0h + cw * 8);            \
            }                                                                    \
        }                                                                        \
        cpa_commit();                                                            \
    } while (0)

    TG_ISSUE(0);
    TG_ISSUE(1);

    for (int c = 0; c < nch; c++) {
        cpa_wait1();
        __syncthreads();
        uint32_t* As = sm + (c & 1) * 2 * TILE_W;
        uint32_t* Bs = As + TILE_W;
#pragma unroll
        for (int ks = 0; ks < 2; ks++) {
            int kb = ks * 8;
            uint32_t af[2][4];
#pragma unroll
            for (int mt = 0; mt < 2; mt++) {
                int r = wm + mt * 16 + g;
                af[mt][0] = As[r * LDW + kb + tg];
                af[mt][1] = As[(r + 8) * LDW + kb + tg];
                af[mt][2] = As[r * LDW + kb + tg + 4];
                af[mt][3] = As[(r + 8) * LDW + kb + tg + 4];
            }
            uint32_t bf[8][2];
#pragma unroll
            for (int nt = 0; nt < 8; nt++) {
                int n = wn + nt * 8 + g;
                bf[nt][0] = Bs[n * LDW + kb + tg];
                bf[nt][1] = Bs[n * LDW + kb + tg + 4];
            }
#pragma unroll
            for (int mt = 0; mt < 2; mt++)
#pragma unroll
                for (int nt = 0; nt < 8; nt++)
                    mma16n8k16(acc[mt][nt], af[mt], bf[nt]);
        }
        __syncthreads();
        TG_ISSUE(c + 2);
    }
#undef TG_ISSUE

    bool do_relu = flags & 1, half_out = flags & 2;
    __half* Ch = g_hbuf + offC;
    float*  Cf = g_scratch + offC;
#pragma unroll
    for (int mt = 0; mt < 2; mt++) {
        int r0 = m0 + wm + mt * 16 + g;
#pragma unroll
        for (int nt = 0; nt < 8; nt++) {
            int col = n0 + wn + nt * 8 + 2 * tg;
            float bz0 = bias[col], bz1 = bias[col + 1];
            float v0 = acc[mt][nt][0] + bz0, v1 = acc[mt][nt][1] + bz1;
            float v2 = acc[mt][nt][2] + bz0, v3 = acc[mt][nt][3] + bz1;
            if (do_relu) {
                v0 = fmaxf(v0, 0.f); v1 = fmaxf(v1, 0.f);
                v2 = fmaxf(v2, 0.f); v3 = fmaxf(v3, 0.f);
            }
            if (half_out) {
                __half2 pa = __floats2half2_rn(v0, v1);
                __half2 pb = __floats2half2_rn(v2, v3);
                if (r0 < M)     *(__half2*)(Ch + (size_t)r0 * ldc + col) = pa;
                if (r0 + 8 < M) *(__half2*)(Ch + (size_t)(r0 + 8) * ldc + col) = pb;
            } else {
                if (r0 < M) {
                    Cf[(size_t)r0 * ldc + col] = v0;
                    Cf[(size_t)r0 * ldc + col + 1] = v1;
                }
                if (r0 + 8 < M) {
                    Cf[(size_t)(r0 + 8) * ldc + col] = v2;
                    Cf[(size_t)(r0 + 8) * ldc + col + 1] = v3;
                }
            }
        }
    }
}

// ---------------------------------------------------------------------------
// Copy sampled xyz (float scratch) into trailing 3 cols of a half concat buf
// ---------------------------------------------------------------------------
__global__ void copy3_kernel(long long src_off, long long dst_hoff, int ldd, int rows)
{
    int r = blockIdx.x * blockDim.x + threadIdx.x;
    if (r >= rows) return;
    const float* s = g_scratch + src_off + (size_t)r * 3;
    __half* d = g_hbuf + dst_hoff + (size_t)r * ldd;
    d[0] = __float2half_rn(s[0]);
    d[1] = __float2half_rn(s[1]);
    d[2] = __float2half_rn(s[2]);
}

// ---------------------------------------------------------------------------
// Gather 384-wide half feature rows at FPS indices (uint4 = 8 halves)
// ---------------------------------------------------------------------------
__global__ void gather384_kernel(long long src_hoff, int srcS,
                                 long long dst_hoff, int idx_off, int S, int total8)
{
    int e = blockIdx.x * blockDim.x + threadIdx.x;
    if (e >= total8) return;
    int r = e / 48, c = e - r * 48;
    int b = r / S;
    int idx = g_idx[idx_off + r];
    const uint4* s = (const uint4*)(g_hbuf + src_hoff);
    uint4* d = (uint4*)(g_hbuf + dst_hoff);
    d[(size_t)r * 48 + c] = s[((size_t)b * srcS + idx) * 48 + c];
}

// ---------------------------------------------------------------------------
// Max-pool l8 (fp32) over 125 sampled points per batch
// ---------------------------------------------------------------------------
__global__ void maxpool_kernel(float* __restrict__ out)
{
    int e = blockIdx.x * blockDim.x + threadIdx.x;
    if (e >= BATCH * 512) return;
    int b = e >> 9, c = e & 511;
    const float* base = g_scratch + OFF_L8 + (size_t)b * S3 * 512 + c;
    float m = base[0];
    for (int s = 1; s < S3; s++) m = fmaxf(m, base[(size_t)s * 512]);
    out[e] = m;
}

// ---------------------------------------------------------------------------
// Launch
// ---------------------------------------------------------------------------
extern "C" void kernel_launch(void* const* d_in, const int* in_sizes, int n_in,
                              void* d_out, int out_size)
{
    const float* x    = (const float*)d_in[0];
    const float* cw1  = (const float*)d_in[1];
    const float* cb1  = (const float*)d_in[2];
    const float* cw2  = (const float*)d_in[3];
    const float* cb2  = (const float*)d_in[4];
    const float* w1   = (const float*)d_in[5];
    const float* b1   = (const float*)d_in[6];
    const float* w2   = (const float*)d_in[7];
    const float* b2   = (const float*)d_in[8];
    const float* w3   = (const float*)d_in[9];
    const float* b3   = (const float*)d_in[10];
    const float* w4   = (const float*)d_in[11];
    const float* b4   = (const float*)d_in[12];
    const float* w5   = (const float*)d_in[13];
    const float* b5   = (const float*)d_in[14];
    const float* w6   = (const float*)d_in[15];
    const float* b6   = (const float*)d_in[16];
    const float* pc1w = (const float*)d_in[17];
    const float* pc1b = (const float*)d_in[18];
    const float* pc2w = (const float*)d_in[19];
    const float* pc2b = (const float*)d_in[20];

    float* out  = (float*)d_out;            // (B,512)
    float* conf = out + BATCH * 512;        // (B,N,1)

    cudaFuncSetAttribute(tgemm_kernel, cudaFuncAttributeMaxDynamicSharedMemorySize,
                         TG_SMEM);
    cudaFuncSetAttribute(fps_kernel<512, 8>, cudaFuncAttributeMaxDynamicSharedMemorySize,
                         3 * NPTS * 4 + 1024);

    wconv_kernel<<<(WC_TOTAL + 255) / 256, 256>>>(w2, pc1w, w3, w4, pc2w, w5, w6);
    conf_kernel<<<(BATCH * NPTS + 255) / 256, 256>>>(x, cw1, cb1, cw2, cb2, conf);

    fps_kernel<512, 8><<<BATCH, 512, 3 * NPTS * 4 + 1024>>>(
        x, -1LL, NPTS, S1, IDX1, (long long)OFF_NX1);

    build_fcg<<<(M1 + 255) / 256, 256>>>(x, conf);
    layer1_kernel<<<(M1 * 16 + 255) / 256, 256>>>(w1, b1);

    // h1 @ w2 -> l2g   [32000,64]x[64,256]   relu, half out
    tgemm_kernel<<<dim3(M1 / 128, 2), 256, TG_SMEM>>>(
        (long long)HOFF_H1, 64, (long long)(HOFF_WC + WC_W2), b2,
        (long long)HOFF_L2G, 256, M1, 256, 64, 3);
    // l2g @ pc1w -> cat1[:,0:256]   half out (aligned)
    tgemm_kernel<<<dim3(M1 / 128, 2), 256, TG_SMEM>>>(
        (long long)HOFF_L2G, 256, (long long)(HOFF_WC + WC_PC1), pc1b,
        (long long)HOFF_CAT1, 264, M1, 256, 256, 2);
    copy3_kernel<<<(M1 + 255) / 256, 256>>>((long long)OFF_NX1,
                                            (long long)(HOFF_CAT1 + 256), 264, M1);
    // cat1 @ w3(permuted) -> l4   [32000,288pad]x[.,256]   relu, half out
    tgemm_kernel<<<dim3(M1 / 128, 2), 256, TG_SMEM>>>(
        (long long)HOFF_CAT1, 264, (long long)(HOFF_WC + WC_W3), b3,
        (long long)HOFF_L4, 256, M1, 256, 288, 3);
    // l4 @ w4 -> l5   [32000,256]x[256,384]   relu, half out
    tgemm_kernel<<<dim3(M1 / 128, 3), 256, TG_SMEM>>>(
        (long long)HOFF_L4, 256, (long long)(HOFF_WC + WC_W4), b4,
        (long long)HOFF_L5, 384, M1, 384, 256, 3);

    fps_kernel<256, 2><<<BATCH, 256, 3 * S1 * 4 + 1024>>>(
        nullptr, (long long)OFF_NX1, S1, S2, IDX2, (long long)OFF_NX2);
    gather384_kernel<<<(M2 * 48 + 255) / 256, 256>>>((long long)HOFF_L5, S1,
                                                     (long long)HOFF_NF2, IDX2, S2, M2 * 48);

    // nf2 @ pc2w -> cat2[:,0:384]   half out (aligned)
    tgemm_kernel<<<dim3(M2 / 128, 3), 256, TG_SMEM>>>(
        (long long)HOFF_NF2, 384, (long long)(HOFF_WC + WC_PC2), pc2b,
        (long long)HOFF_CAT2, 392, M2, 384, 384, 2);
    copy3_kernel<<<(M2 + 255) / 256, 256>>>((long long)OFF_NX2,
                                            (long long)(HOFF_CAT2 + 384), 392, M2);
    // cat2 @ w5(permuted) -> l7   [16000,416pad]x[.,384]   relu, half out
    tgemm_kernel<<<dim3(M2 / 128, 3), 256, TG_SMEM>>>(
        (long long)HOFF_CAT2, 392, (long long)(HOFF_WC + WC_W5), b5,
        (long long)HOFF_L7, 384, M2, 384, 416, 3);

    fps_kernel<128, 2><<<BATCH, 128, 3 * S2 * 4 + 1024>>>(
        nullptr, (long long)OFF_NX2, S2, S3, IDX3, -1LL);
    gather384_kernel<<<(M3 * 48 + 255) / 256, 256>>>((long long)HOFF_L7, S2,
                                                     (long long)HOFF_NF3, IDX3, S3, M3 * 48);

    // nf3 @ w6 -> l8   [8000,384]x[384,512]   relu, fp32 out (final)
    tgemm_kernel<<<dim3((M3 + 127) / 128, 4), 256, TG_SMEM>>>(
        (long long)HOFF_NF3, 384, (long long)(HOFF_WC + WC_W6), b6,
        (long long)OFF_L8, 512, M3, 512, 384, 1);
    maxpool_kernel<<<(BATCH * 512 + 255) / 256, 256>>>(out);
}

// round 8
// speedup vs baseline: 2.9616x; 1.1668x over previous
#include <cuda_runtime.h>
#include <cuda_fp16.h>
#include <math.h>
#include <cstdint>

// ---------------------------------------------------------------------------
// Problem constants
// ---------------------------------------------------------------------------
#define BATCH 64
#define NPTS  4096

constexpr int S1 = 500, S2 = 250, S3 = 125;
constexpr int M1 = BATCH * S1;   // 32000
constexpr int M2 = BATCH * S2;   // 16000
constexpr int M3 = BATCH * S3;   // 8000

// ---------------------------------------------------------------------------
// Float scratch (coords, final l8)
// ---------------------------------------------------------------------------
constexpr size_t OFF_NX1 = 0;                          // [M1,3]
constexpr size_t OFF_NX2 = OFF_NX1 + (size_t)M1 * 3;   // [M2,3]
constexpr size_t OFF_L8  = OFF_NX2 + (size_t)M2 * 3;   // [M3,512]
constexpr size_t SCRATCH_SZ = OFF_L8 + (size_t)M3 * 512;

// ---------------------------------------------------------------------------
// Half buffer. Concats are FEATURE-FIRST: cat = [feat | xyz]; w3/w5 K-permuted.
// ---------------------------------------------------------------------------
constexpr size_t HOFF_H1   = 0;                               // [M1,64]
constexpr size_t HOFF_L2G  = HOFF_H1   + (size_t)M1 * 64;     // [M1,256]
constexpr size_t HOFF_CAT1 = HOFF_L2G  + (size_t)M1 * 256;    // [M1,264]
constexpr size_t HOFF_L4   = HOFF_CAT1 + (size_t)M1 * 264;    // [M1,256]
constexpr size_t HOFF_L5   = HOFF_L4   + (size_t)M1 * 256;    // [M1,384]
constexpr size_t HOFF_CAT2 = HOFF_L5   + (size_t)M1 * 384;    // [M2,392]
constexpr size_t HOFF_L7   = HOFF_CAT2 + (size_t)M2 * 392;    // [M2,384]
constexpr size_t HOFF_WC   = HOFF_L7   + (size_t)M2 * 384;
constexpr int WC_W2  = 0;        // Kpad  64, N 256
constexpr int WC_PC1 = 16384;    // Kpad 256, N 256
constexpr int WC_W3  = 81920;    // Kpad 288, N 256  (K-permuted)
constexpr int WC_W4  = 155648;   // Kpad 256, N 384
constexpr int WC_PC2 = 253952;   // Kpad 384, N 384
constexpr int WC_W5  = 401408;   // Kpad 416, N 384  (K-permuted)
constexpr int WC_W6  = 561152;   // Kpad 384, N 512
constexpr int WC_TOTAL = 757760;
constexpr size_t HBUF_SZ = HOFF_WC + WC_TOTAL;

__device__ __align__(256) float  g_scratch[SCRATCH_SZ];
__device__ __align__(256) __half g_hbuf[HBUF_SZ];
__device__ int g_idx[M1 + M2 + M3];
constexpr int IDX1 = 0, IDX2 = M1, IDX3 = M1 + M2;

// ---------------------------------------------------------------------------
// PTX helpers
// ---------------------------------------------------------------------------
__device__ __forceinline__ void mma16n8k16(float* c, const uint32_t* a, const uint32_t* b) {
    asm volatile(
        "mma.sync.aligned.m16n8k16.row.col.f32.f16.f16.f32 "
        "{%0,%1,%2,%3}, {%4,%5,%6,%7}, {%8,%9}, {%0,%1,%2,%3};"
        : "+f"(c[0]), "+f"(c[1]), "+f"(c[2]), "+f"(c[3])
        : "r"(a[0]), "r"(a[1]), "r"(a[2]), "r"(a[3]), "r"(b[0]), "r"(b[1]));
}
__device__ __forceinline__ void ldsm4(uint32_t& r0, uint32_t& r1, uint32_t& r2,
                                      uint32_t& r3, uint32_t addr) {
    asm volatile("ldmatrix.sync.aligned.m8n8.x4.shared.b16 {%0,%1,%2,%3}, [%4];"
                 : "=r"(r0), "=r"(r1), "=r"(r2), "=r"(r3) : "r"(addr));
}
__device__ __forceinline__ uint32_t smem_u32(const void* p) {
    uint32_t a;
    asm("{ .reg .u64 t; cvta.to.shared.u64 t, %1; cvt.u32.u64 %0, t; }"
        : "=r"(a) : "l"(p));
    return a;
}
__device__ __forceinline__ void cpa16(uint32_t dst, const __half* src) {
    asm volatile("cp.async.ca.shared.global [%0], [%1], 16;"
                 :: "r"(dst), "l"(src) : "memory");
}
__device__ __forceinline__ void cpa_commit() {
    asm volatile("cp.async.commit_group;" ::: "memory");
}
__device__ __forceinline__ void cpa_wait1() {
    asm volatile("cp.async.wait_group 1;" ::: "memory");
}

// ---------------------------------------------------------------------------
// Confidence MLP
// ---------------------------------------------------------------------------
__global__ void conf_kernel(const float* __restrict__ x,
                            const float* __restrict__ cw1,
                            const float* __restrict__ cb1,
                            const float* __restrict__ cw2,
                            const float* __restrict__ cb2,
                            float* __restrict__ conf)
{
    int p = blockIdx.x * blockDim.x + threadIdx.x;
    if (p >= BATCH * NPTS) return;
    float x0 = x[3 * p], x1 = x[3 * p + 1], x2 = x[3 * p + 2];
    float acc = 0.f;
#pragma unroll 8
    for (int j = 0; j < 64; j++) {
        float h = cb1[j] + x0 * cw1[j] + x1 * cw1[64 + j] + x2 * cw1[128 + j];
        h = fmaxf(h, 0.f);
        acc += h * cw2[j];
    }
    float z = acc + cb2[0];
    conf[p] = 1.f / (1.f + expf(-z));
}

// ---------------------------------------------------------------------------
// Weight preconversion -> fp16, transposed [N][Kpad], 0-pad, K-permute w3/w5
// ---------------------------------------------------------------------------
__global__ void wconv_kernel(const float* __restrict__ w2, const float* __restrict__ pc1w,
                             const float* __restrict__ w3, const float* __restrict__ w4,
                             const float* __restrict__ pc2w, const float* __restrict__ w5,
                             const float* __restrict__ w6)
{
    int e = blockIdx.x * blockDim.x + threadIdx.x;
    if (e >= WC_TOTAL) return;
    const float* src; int base, N, K, Kpad, perm3;
    if (e < WC_PC1)      { src = w2;   base = WC_W2;  N = 256; K = 64;  Kpad = 64;  perm3 = 0; }
    else if (e < WC_W4)  {
        if (e < WC_W3)   { src = pc1w; base = WC_PC1; N = 256; K = 256; Kpad = 256; perm3 = 0; }
        else             { src = w3;   base = WC_W3;  N = 256; K = 259; Kpad = 288; perm3 = 1; }
    }
    else if (e < WC_PC2) { src = w4;   base = WC_W4;  N = 384; K = 256; Kpad = 256; perm3 = 0; }
    else if (e < WC_W5)  { src = pc2w; base = WC_PC2; N = 384; K = 384; Kpad = 384; perm3 = 0; }
    else if (e < WC_W6)  { src = w5;   base = WC_W5;  N = 384; K = 387; Kpad = 416; perm3 = 1; }
    else                 { src = w6;   base = WC_W6;  N = 512; K = 384; Kpad = 384; perm3 = 0; }
    int local = e - base;
    int n = local / Kpad, k = local - n * Kpad;
    float v = 0.f;
    if (k < K) {
        int ks = perm3 ? ((k < K - 3) ? k + 3 : k - (K - 3)) : k;
        v = __ldg(&src[(size_t)ks * N + n]);
    }
    g_hbuf[HOFF_WC + e] = __float2half_rn(v);
}

// ---------------------------------------------------------------------------
// Farthest point sampling (known-good, 1 barrier/iter)
// ---------------------------------------------------------------------------
template <int BDIM, int PT>
__global__ void fps_kernel(const float* __restrict__ pts_ext, long long pts_off,
                           int n, int npoint, int idx_off, long long nx_off)
{
    extern __shared__ float sh[];
    float* spx = sh;
    float* spy = sh + n;
    float* spz = sh + 2 * n;
    unsigned long long* skey = (unsigned long long*)(sh + 3 * n + (3 * n & 1));

    const float* pts = (pts_off >= 0) ? (g_scratch + pts_off) : pts_ext;
    int b = blockIdx.x;
    pts += (size_t)b * n * 3;
    int tid = threadIdx.x, lane = tid & 31;
    int wid = tid >> 5;
    constexpr int NW = BDIM / 32;

    float px[PT], py[PT], pz[PT], dist[PT];
    {
        int t = 0;
        for (int i = tid; i < n; i += BDIM, t++) {
            float a = pts[3 * i], bb = pts[3 * i + 1], cc = pts[3 * i + 2];
            spx[i] = a; spy[i] = bb; spz[i] = cc;
            px[t] = a; py[t] = bb; pz[t] = cc; dist[t] = 1e10f;
        }
    }
    __syncthreads();

    int far = 0;
    for (int s = 0; s < npoint; s++) {
        if (tid == 0) {
            g_idx[idx_off + b * npoint + s] = far;
            if (nx_off >= 0) {
                float* o = g_scratch + nx_off + ((size_t)b * npoint + s) * 3;
                o[0] = spx[far]; o[1] = spy[far]; o[2] = spz[far];
            }
        }
        float cx = spx[far], cy = spy[far], cz = spz[far];

        unsigned long long best = 0ull;
#pragma unroll
        for (int t = 0; t < PT; t++) {
            int gi = tid + t * BDIM;
            if (gi < n) {
                float dx = px[t] - cx, dy = py[t] - cy, dz = pz[t] - cz;
                float d = dx * dx + dy * dy + dz * dz;
                if (d < dist[t]) dist[t] = d;
                unsigned long long key =
                    ((unsigned long long)__float_as_uint(dist[t]) << 32) |
                    (unsigned)(~gi);
                if (key > best) best = key;
            }
        }
#pragma unroll
        for (int off = 16; off; off >>= 1) {
            unsigned long long o = __shfl_down_sync(0xffffffffu, best, off);
            if (o > best) best = o;
        }
        int par = s & 1;
        if (lane == 0) skey[par * 32 + wid] = best;
        __syncthreads();
        unsigned long long k2 = (lane < NW) ? skey[par * 32 + lane] : 0ull;
#pragma unroll
        for (int off = 16; off; off >>= 1) {
            unsigned long long o = __shfl_xor_sync(0xffffffffu, k2, off);
            if (o > k2) k2 = o;
        }
        far = (int)(~(unsigned)k2);
    }
}

// ---------------------------------------------------------------------------
// Fused layer-1: h1 = relu([conf,x]@w1 + b1) at FPS-1 points; fp16 out
// ---------------------------------------------------------------------------
__global__ void layer1_kernel(const float* __restrict__ x, const float* __restrict__ conf,
                              const float* __restrict__ w1, const float* __restrict__ b1)
{
    int gid = blockIdx.x * blockDim.x + threadIdx.x;
    if (gid >= M1 * 16) return;
    int r = gid >> 4, q = (gid & 15) * 4;
    int b = r / S1;
    int idx = g_idx[IDX1 + r];
    size_t pbase = (size_t)b * NPTS + idx;
    float a0 = conf[pbase];
    float a1 = x[pbase * 3], a2 = x[pbase * 3 + 1], a3 = x[pbase * 3 + 2];
    float o[4];
#pragma unroll
    for (int j = 0; j < 4; j++) {
        float v = b1[q + j];
        v += a0 * __ldg(&w1[0 * 64 + q + j]);
        v += a1 * __ldg(&w1[1 * 64 + q + j]);
        v += a2 * __ldg(&w1[2 * 64 + q + j]);
        v += a3 * __ldg(&w1[3 * 64 + q + j]);
        o[j] = fmaxf(v, 0.f);
    }
    __half2 p0 = __floats2half2_rn(o[0], o[1]);
    __half2 p1 = __floats2half2_rn(o[2], o[3]);
    uint2 pk = make_uint2(*(uint32_t*)&p0, *(uint32_t*)&p1);
    *(uint2*)(g_hbuf + HOFF_H1 + (size_t)r * 64 + q) = pk;
}

// ---------------------------------------------------------------------------
// fp16 HMMA GEMM, cp.async double-buffered, ldmatrix fragments, optional
// row-gather on A (idx_off >= 0: src row = (r/Sdst)*Ssrc + g_idx[idx_off+r]).
// flags: bit0 = relu, bit1 = half out (g_hbuf) else fp32 (g_scratch).
// ---------------------------------------------------------------------------
constexpr int LDW = 20;                       // words per smem row (16 + pad)
constexpr int TILE_W = 128 * LDW;
constexpr int TILE_B = TILE_W * 4;            // 10240 bytes
constexpr int TG_SMEM = 4 * TILE_B;           // 40960 bytes

__global__ void __launch_bounds__(256)
tgemm_kernel(long long hoffA, int lda, long long hoffW, const float* __restrict__ bias,
             long long offC, int ldc, int M, int N, int Kpad, int flags,
             int idx_off, int Sdst, int Ssrc)
{
    extern __shared__ uint32_t sm[];
    const __half* Wh = g_hbuf + hoffW;

    int tid = threadIdx.x, lane = tid & 31, wid = tid >> 5;
    int m0 = blockIdx.x * 128, n0 = blockIdx.y * 128;
    int wm = (wid >> 1) * 32, wn = (wid & 1) * 64;
    int g = lane >> 2, tg = lane & 3;

    float acc[2][8][4];
#pragma unroll
    for (int i = 0; i < 2; i++)
#pragma unroll
        for (int j = 0; j < 8; j++)
#pragma unroll
            for (int q = 0; q < 4; q++) acc[i][j][q] = 0.f;

    uint32_t sbase = smem_u32(sm);
    int nch = Kpad >> 5;

    // loader roles: rows row0, row0+64; 4 threads per row, 16B each
    int row0 = tid >> 2, cw = tid & 3;
    const __half* aptr[2];
    const __half* bptr[2];
    uint32_t soff[2];
#pragma unroll
    for (int j = 0; j < 2; j++) {
        int rloc = row0 + 64 * j;
        int rg = m0 + rloc;
        if (rg > M - 1) rg = M - 1;
        size_t srow;
        if (idx_off >= 0) {
            int bb = rg / Sdst;
            srow = (size_t)bb * Ssrc + g_idx[idx_off + rg];
        } else {
            srow = rg;
        }
        aptr[j] = g_hbuf + hoffA + srow * lda + cw * 8;
        bptr[j] = Wh + (size_t)(n0 + rloc) * Kpad + cw * 8;
        soff[j] = (rloc * LDW + cw * 4) << 2;
    }

#define TG_ISSUE(c)                                                   \
    do {                                                              \
        if ((c) < nch) {                                              \
            uint32_t aw = sbase + ((c) & 1) * 2 * TILE_B;             \
            uint32_t bw = aw + TILE_B;                                \
            int k0h = (c) * 32;                                       \
            _Pragma("unroll")                                         \
            for (int j = 0; j < 2; j++) {                             \
                cpa16(aw + soff[j], aptr[j] + k0h);                   \
                cpa16(bw + soff[j], bptr[j] + k0h);                   \
            }                                                         \
        }                                                             \
        cpa_commit();                                                 \
    } while (0)

    TG_ISSUE(0);
    TG_ISSUE(1);

    // ldmatrix lane offsets (bytes within tile)
    uint32_t aoff = (((wm + (lane & 15)) * LDW + ((lane >> 4) << 2)) << 2);
    uint32_t boff = (((wn + ((lane >> 4)) * 8 + (lane & 7)) * LDW +
                      (((lane >> 3) & 1) << 2)) << 2);

    for (int c = 0; c < nch; c++) {
        cpa_wait1();
        __syncthreads();
        uint32_t Ab = sbase + (c & 1) * 2 * TILE_B;
        uint32_t Bb = Ab + TILE_B;
#pragma unroll
        for (int ks = 0; ks < 2; ks++) {
            uint32_t af[2][4];
#pragma unroll
            for (int mt = 0; mt < 2; mt++)
                ldsm4(af[mt][0], af[mt][1], af[mt][2], af[mt][3],
                      Ab + aoff + mt * 16 * LDW * 4 + ks * 32);
            uint32_t bf[8][2];
#pragma unroll
            for (int np = 0; np < 4; np++)
                ldsm4(bf[2 * np][0], bf[2 * np][1], bf[2 * np + 1][0], bf[2 * np + 1][1],
                      Bb + boff + np * 16 * LDW * 4 + ks * 32);
#pragma unroll
            for (int mt = 0; mt < 2; mt++)
#pragma unroll
                for (int nt = 0; nt < 8; nt++)
                    mma16n8k16(acc[mt][nt], af[mt], bf[nt]);
        }
        __syncthreads();
        TG_ISSUE(c + 2);
    }
#undef TG_ISSUE

    bool do_relu = flags & 1, half_out = flags & 2;
    __half* Ch = g_hbuf + offC;
    float*  Cf = g_scratch + offC;
#pragma unroll
    for (int mt = 0; mt < 2; mt++) {
        int r0 = m0 + wm + mt * 16 + g;
#pragma unroll
        for (int nt = 0; nt < 8; nt++) {
            int col = n0 + wn + nt * 8 + 2 * tg;
            float bz0 = bias[col], bz1 = bias[col + 1];
            float v0 = acc[mt][nt][0] + bz0, v1 = acc[mt][nt][1] + bz1;
            float v2 = acc[mt][nt][2] + bz0, v3 = acc[mt][nt][3] + bz1;
            if (do_relu) {
                v0 = fmaxf(v0, 0.f); v1 = fmaxf(v1, 0.f);
                v2 = fmaxf(v2, 0.f); v3 = fmaxf(v3, 0.f);
            }
            if (half_out) {
                __half2 pa = __floats2half2_rn(v0, v1);
                __half2 pb = __floats2half2_rn(v2, v3);
                if (r0 < M)     *(__half2*)(Ch + (size_t)r0 * ldc + col) = pa;
                if (r0 + 8 < M) *(__half2*)(Ch + (size_t)(r0 + 8) * ldc + col) = pb;
            } else {
                if (r0 < M) {
                    Cf[(size_t)r0 * ldc + col] = v0;
                    Cf[(size_t)r0 * ldc + col + 1] = v1;
                }
                if (r0 + 8 < M) {
                    Cf[(size_t)(r0 + 8) * ldc + col] = v2;
                    Cf[(size_t)(r0 + 8) * ldc + col + 1] = v3;
                }
            }
        }
    }
}

// ---------------------------------------------------------------------------
// Copy sampled xyz into trailing 3 cols of a half concat buffer
// ---------------------------------------------------------------------------
__global__ void copy3_kernel(long long src_off, long long dst_hoff, int ldd, int rows)
{
    int r = blockIdx.x * blockDim.x + threadIdx.x;
    if (r >= rows) return;
    const float* s = g_scratch + src_off + (size_t)r * 3;
    __half* d = g_hbuf + dst_hoff + (size_t)r * ldd;
    d[0] = __float2half_rn(s[0]);
    d[1] = __float2half_rn(s[1]);
    d[2] = __float2half_rn(s[2]);
}

// ---------------------------------------------------------------------------
// Max-pool l8 (fp32) over 125 sampled points per batch
// ---------------------------------------------------------------------------
__global__ void maxpool_kernel(float* __restrict__ out)
{
    int e = blockIdx.x * blockDim.x + threadIdx.x;
    if (e >= BATCH * 512) return;
    int b = e >> 9, c = e & 511;
    const float* base = g_scratch + OFF_L8 + (size_t)b * S3 * 512 + c;
    float m = base[0];
    for (int s = 1; s < S3; s++) m = fmaxf(m, base[(size_t)s * 512]);
    out[e] = m;
}

// ---------------------------------------------------------------------------
// Launch: FPS chain on a side stream, forked/joined via events so fps2/fps3
// overlap the stage-1 GEMM chain under graph capture.
// ---------------------------------------------------------------------------
extern "C" void kernel_launch(void* const* d_in, const int* in_sizes, int n_in,
                              void* d_out, int out_size)
{
    const float* x    = (const float*)d_in[0];
    const float* cw1  = (const float*)d_in[1];
    const float* cb1  = (const float*)d_in[2];
    const float* cw2  = (const float*)d_in[3];
    const float* cb2  = (const float*)d_in[4];
    const float* w1   = (const float*)d_in[5];
    const float* b1   = (const float*)d_in[6];
    const float* w2   = (const float*)d_in[7];
    const float* b2   = (const float*)d_in[8];
    const float* w3   = (const float*)d_in[9];
    const float* b3   = (const float*)d_in[10];
    const float* w4   = (const float*)d_in[11];
    const float* b4   = (const float*)d_in[12];
    const float* w5   = (const float*)d_in[13];
    const float* b5   = (const float*)d_in[14];
    const float* w6   = (const float*)d_in[15];
    const float* b6   = (const float*)d_in[16];
    const float* pc1w = (const float*)d_in[17];
    const float* pc1b = (const float*)d_in[18];
    const float* pc2w = (const float*)d_in[19];
    const float* pc2b = (const float*)d_in[20];

    float* out  = (float*)d_out;            // (B,512)
    float* conf = out + BATCH * 512;        // (B,N,1)

    static cudaStream_t s1 = nullptr;
    static cudaEvent_t evFork, evF1, evF2, evF3;
    if (!s1) {
        cudaStreamCreateWithFlags(&s1, cudaStreamNonBlocking);
        cudaEventCreateWithFlags(&evFork, cudaEventDisableTiming);
        cudaEventCreateWithFlags(&evF1, cudaEventDisableTiming);
        cudaEventCreateWithFlags(&evF2, cudaEventDisableTiming);
        cudaEventCreateWithFlags(&evF3, cudaEventDisableTiming);
        cudaFuncSetAttribute(tgemm_kernel, cudaFuncAttributeMaxDynamicSharedMemorySize,
                             TG_SMEM);
        cudaFuncSetAttribute(fps_kernel<512, 8>,
                             cudaFuncAttributeMaxDynamicSharedMemorySize,
                             3 * NPTS * 4 + 1024);
    }

    // Fork side stream for the serial FPS chain
    cudaEventRecord(evFork, 0);
    cudaStreamWaitEvent(s1, evFork, 0);
    fps_kernel<512, 8><<<BATCH, 512, 3 * NPTS * 4 + 1024, s1>>>(
        x, -1LL, NPTS, S1, IDX1, (long long)OFF_NX1);
    cudaEventRecord(evF1, s1);
    fps_kernel<256, 2><<<BATCH, 256, 3 * S1 * 4 + 1024, s1>>>(
        nullptr, (long long)OFF_NX1, S1, S2, IDX2, (long long)OFF_NX2);
    cudaEventRecord(evF2, s1);
    fps_kernel<128, 2><<<BATCH, 128, 3 * S2 * 4 + 1024, s1>>>(
        nullptr, (long long)OFF_NX2, S2, S3, IDX3, -1LL);
    cudaEventRecord(evF3, s1);

    // Main stream: weight conversion + conf overlap fps1
    wconv_kernel<<<(WC_TOTAL + 255) / 256, 256>>>(w2, pc1w, w3, w4, pc2w, w5, w6);
    conf_kernel<<<(BATCH * NPTS + 255) / 256, 256>>>(x, cw1, cb1, cw2, cb2, conf);

    cudaStreamWaitEvent(0, evF1, 0);
    layer1_kernel<<<(M1 * 16 + 255) / 256, 256>>>(x, conf, w1, b1);

    // h1 @ w2 -> l2g
    tgemm_kernel<<<dim3(M1 / 128, 2), 256, TG_SMEM>>>(
        (long long)HOFF_H1, 64, (long long)(HOFF_WC + WC_W2), b2,
        (long long)HOFF_L2G, 256, M1, 256, 64, 3, -1, 0, 0);
    // l2g @ pc1w -> cat1[:,0:256]
    tgemm_kernel<<<dim3(M1 / 128, 2), 256, TG_SMEM>>>(
        (long long)HOFF_L2G, 256, (long long)(HOFF_WC + WC_PC1), pc1b,
        (long long)HOFF_CAT1, 264, M1, 256, 256, 2, -1, 0, 0);
    copy3_kernel<<<(M1 + 255) / 256, 256>>>((long long)OFF_NX1,
                                            (long long)(HOFF_CAT1 + 256), 264, M1);
    // cat1 @ w3p -> l4
    tgemm_kernel<<<dim3(M1 / 128, 2), 256, TG_SMEM>>>(
        (long long)HOFF_CAT1, 264, (long long)(HOFF_WC + WC_W3), b3,
        (long long)HOFF_L4, 256, M1, 256, 288, 3, -1, 0, 0);
    // l4 @ w4 -> l5
    tgemm_kernel<<<dim3(M1 / 128, 3), 256, TG_SMEM>>>(
        (long long)HOFF_L4, 256, (long long)(HOFF_WC + WC_W4), b4,
        (long long)HOFF_L5, 384, M1, 384, 256, 3, -1, 0, 0);

    cudaStreamWaitEvent(0, evF2, 0);
    // gather(l5, idx2) @ pc2w -> cat2[:,0:384]
    tgemm_kernel<<<dim3(M2 / 128, 3), 256, TG_SMEM>>>(
        (long long)HOFF_L5, 384, (long long)(HOFF_WC + WC_PC2), pc2b,
        (long long)HOFF_CAT2, 392, M2, 384, 384, 2, IDX2, S2, S1);
    copy3_kernel<<<(M2 + 255) / 256, 256>>>((long long)OFF_NX2,
                                            (long long)(HOFF_CAT2 + 384), 392, M2);
    // cat2 @ w5p -> l7
    tgemm_kernel<<<dim3(M2 / 128, 3), 256, TG_SMEM>>>(
        (long long)HOFF_CAT2, 392, (long long)(HOFF_WC + WC_W5), b5,
        (long long)HOFF_L7, 384, M2, 384, 416, 3, -1, 0, 0);

    cudaStreamWaitEvent(0, evF3, 0);
    // gather(l7, idx3) @ w6 -> l8 (fp32)
    tgemm_kernel<<<dim3((M3 + 127) / 128, 4), 256, TG_SMEM>>>(
        (long long)HOFF_L7, 384, (long long)(HOFF_WC + WC_W6), b6,
        (long long)OFF_L8, 512, M3, 512, 384, 1, IDX3, S3, S2);
    maxpool_kernel<<<(BATCH * 512 + 255) / 256, 256>>>(out);
}

// round 9
// speedup vs baseline: 3.4023x; 1.1488x over previous
#include <cuda_runtime.h>
#include <cuda_fp16.h>
#include <math.h>
#include <cstdint>

// ---------------------------------------------------------------------------
// Problem constants
// ---------------------------------------------------------------------------
#define BATCH 64
#define NPTS  4096

constexpr int S1 = 500, S2 = 250, S3 = 125;
constexpr int M1 = BATCH * S1;   // 32000
constexpr int M2 = BATCH * S2;   // 16000
constexpr int M3 = BATCH * S3;   // 8000

// ---------------------------------------------------------------------------
// Float scratch (coords, final l8)
// ---------------------------------------------------------------------------
constexpr size_t OFF_NX1 = 0;                          // [M1,3]
constexpr size_t OFF_NX2 = OFF_NX1 + (size_t)M1 * 3;   // [M2,3]
constexpr size_t OFF_L8  = OFF_NX2 + (size_t)M2 * 3;   // [M3,512]
constexpr size_t SCRATCH_SZ = OFF_L8 + (size_t)M3 * 512;

// ---------------------------------------------------------------------------
// Half buffer. Concats are FEATURE-FIRST: cat = [feat | xyz]; w3/w5 K-permuted.
// ---------------------------------------------------------------------------
constexpr size_t HOFF_H1   = 0;                               // [M1,64]
constexpr size_t HOFF_L2G  = HOFF_H1   + (size_t)M1 * 64;     // [M1,256]
constexpr size_t HOFF_CAT1 = HOFF_L2G  + (size_t)M1 * 256;    // [M1,264]
constexpr size_t HOFF_L4   = HOFF_CAT1 + (size_t)M1 * 264;    // [M1,256]
constexpr size_t HOFF_L5   = HOFF_L4   + (size_t)M1 * 256;    // [M1,384]
constexpr size_t HOFF_CAT2 = HOFF_L5   + (size_t)M1 * 384;    // [M2,392]
constexpr size_t HOFF_L7   = HOFF_CAT2 + (size_t)M2 * 392;    // [M2,384]
constexpr size_t HOFF_WC   = HOFF_L7   + (size_t)M2 * 384;
constexpr int WC_W2  = 0;        // Kpad  64, N 256
constexpr int WC_PC1 = 16384;    // Kpad 256, N 256
constexpr int WC_W3  = 81920;    // Kpad 288, N 256  (K-permuted)
constexpr int WC_W4  = 155648;   // Kpad 256, N 384
constexpr int WC_PC2 = 253952;   // Kpad 384, N 384
constexpr int WC_W5  = 401408;   // Kpad 416, N 384  (K-permuted)
constexpr int WC_W6  = 561152;   // Kpad 384, N 512
constexpr int WC_TOTAL = 757760;
constexpr size_t HBUF_SZ = HOFF_WC + WC_TOTAL;

__device__ __align__(256) float  g_scratch[SCRATCH_SZ];
__device__ __align__(256) __half g_hbuf[HBUF_SZ];
__device__ int g_idx[M1 + M2 + M3];
constexpr int IDX1 = 0, IDX2 = M1, IDX3 = M1 + M2;

// ---------------------------------------------------------------------------
// PTX helpers
// ---------------------------------------------------------------------------
__device__ __forceinline__ void mma16n8k16(float* c, const uint32_t* a, const uint32_t* b) {
    asm volatile(
        "mma.sync.aligned.m16n8k16.row.col.f32.f16.f16.f32 "
        "{%0,%1,%2,%3}, {%4,%5,%6,%7}, {%8,%9}, {%0,%1,%2,%3};"
        : "+f"(c[0]), "+f"(c[1]), "+f"(c[2]), "+f"(c[3])
        : "r"(a[0]), "r"(a[1]), "r"(a[2]), "r"(a[3]), "r"(b[0]), "r"(b[1]));
}
__device__ __forceinline__ void ldsm4(uint32_t& r0, uint32_t& r1, uint32_t& r2,
                                      uint32_t& r3, uint32_t addr) {
    asm volatile("ldmatrix.sync.aligned.m8n8.x4.shared.b16 {%0,%1,%2,%3}, [%4];"
                 : "=r"(r0), "=r"(r1), "=r"(r2), "=r"(r3) : "r"(addr));
}
__device__ __forceinline__ uint32_t smem_u32(const void* p) {
    uint32_t a;
    asm("{ .reg .u64 t; cvta.to.shared.u64 t, %1; cvt.u32.u64 %0, t; }"
        : "=r"(a) : "l"(p));
    return a;
}
__device__ __forceinline__ void cpa16(uint32_t dst, const __half* src) {
    asm volatile("cp.async.ca.shared.global [%0], [%1], 16;"
                 :: "r"(dst), "l"(src) : "memory");
}
__device__ __forceinline__ void cpa_commit() {
    asm volatile("cp.async.commit_group;" ::: "memory");
}
__device__ __forceinline__ void cpa_wait2() {
    asm volatile("cp.async.wait_group 2;" ::: "memory");
}
__device__ __forceinline__ uint32_t redux_max(uint32_t v) {
    uint32_t r;
    asm volatile("redux.sync.max.u32 %0, %1, 0xffffffff;" : "=r"(r) : "r"(v));
    return r;
}
__device__ __forceinline__ uint32_t redux_min(uint32_t v) {
    uint32_t r;
    asm volatile("redux.sync.min.u32 %0, %1, 0xffffffff;" : "=r"(r) : "r"(v));
    return r;
}

// ---------------------------------------------------------------------------
// Confidence MLP
// ---------------------------------------------------------------------------
__global__ void conf_kernel(const float* __restrict__ x,
                            const float* __restrict__ cw1,
                            const float* __restrict__ cb1,
                            const float* __restrict__ cw2,
                            const float* __restrict__ cb2,
                            float* __restrict__ conf)
{
    int p = blockIdx.x * blockDim.x + threadIdx.x;
    if (p >= BATCH * NPTS) return;
    float x0 = x[3 * p], x1 = x[3 * p + 1], x2 = x[3 * p + 2];
    float acc = 0.f;
#pragma unroll 8
    for (int j = 0; j < 64; j++) {
        float h = cb1[j] + x0 * cw1[j] + x1 * cw1[64 + j] + x2 * cw1[128 + j];
        h = fmaxf(h, 0.f);
        acc += h * cw2[j];
    }
    float z = acc + cb2[0];
    conf[p] = 1.f / (1.f + expf(-z));
}

// ---------------------------------------------------------------------------
// Weight preconversion -> fp16, transposed [N][Kpad], 0-pad, K-permute w3/w5
// ---------------------------------------------------------------------------
__global__ void wconv_kernel(const float* __restrict__ w2, const float* __restrict__ pc1w,
                             const float* __restrict__ w3, const float* __restrict__ w4,
                             const float* __restrict__ pc2w, const float* __restrict__ w5,
                             const float* __restrict__ w6)
{
    int e = blockIdx.x * blockDim.x + threadIdx.x;
    if (e >= WC_TOTAL) return;
    const float* src; int base, N, K, Kpad, perm3;
    if (e < WC_PC1)      { src = w2;   base = WC_W2;  N = 256; K = 64;  Kpad = 64;  perm3 = 0; }
    else if (e < WC_W4)  {
        if (e < WC_W3)   { src = pc1w; base = WC_PC1; N = 256; K = 256; Kpad = 256; perm3 = 0; }
        else             { src = w3;   base = WC_W3;  N = 256; K = 259; Kpad = 288; perm3 = 1; }
    }
    else if (e < WC_PC2) { src = w4;   base = WC_W4;  N = 384; K = 256; Kpad = 256; perm3 = 0; }
    else if (e < WC_W5)  { src = pc2w; base = WC_PC2; N = 384; K = 384; Kpad = 384; perm3 = 0; }
    else if (e < WC_W6)  { src = w5;   base = WC_W5;  N = 384; K = 387; Kpad = 416; perm3 = 1; }
    else                 { src = w6;   base = WC_W6;  N = 512; K = 384; Kpad = 384; perm3 = 0; }
    int local = e - base;
    int n = local / Kpad, k = local - n * Kpad;
    float v = 0.f;
    if (k < K) {
        int ks = perm3 ? ((k < K - 3) ? k + 3 : k - (K - 3)) : k;
        v = __ldg(&src[(size_t)ks * N + n]);
    }
    g_hbuf[HOFF_WC + e] = __float2half_rn(v);
}

// ---------------------------------------------------------------------------
// Farthest point sampling with redux.sync reductions.
// dist >= 0 -> float bits order-isomorphic to u32. Tie-break = min index
// (thread-local strict '>' keeps earliest t; cross-lane redux.min on idx).
// Matches jnp.argmax first-occurrence semantics exactly.
// ---------------------------------------------------------------------------
template <int BDIM, int PT>
__global__ void fps_kernel(const float* __restrict__ pts_ext, long long pts_off,
                           int n, int npoint, int idx_off, long long nx_off)
{
    extern __shared__ float sh[];
    float* spx = sh;
    float* spy = sh + n;
    float* spz = sh + 2 * n;
    uint32_t* sd = (uint32_t*)(sh + 3 * n);   // [2][32] dist bits
    uint32_t* si = sd + 64;                   // [2][32] idx

    const float* pts = (pts_off >= 0) ? (g_scratch + pts_off) : pts_ext;
    int b = blockIdx.x;
    pts += (size_t)b * n * 3;
    int tid = threadIdx.x, lane = tid & 31;
    int wid = tid >> 5;
    constexpr int NW = BDIM / 32;

    float px[PT], py[PT], pz[PT], dist[PT];
    {
        int t = 0;
        for (int i = tid; i < n; i += BDIM, t++) {
            float a = pts[3 * i], bb = pts[3 * i + 1], cc = pts[3 * i + 2];
            spx[i] = a; spy[i] = bb; spz[i] = cc;
            px[t] = a; py[t] = bb; pz[t] = cc; dist[t] = 1e10f;
        }
    }
    __syncthreads();

    int far = 0;
    for (int s = 0; s < npoint; s++) {
        if (tid == 0) {
            g_idx[idx_off + b * npoint + s] = far;
            if (nx_off >= 0) {
                float* o = g_scratch + nx_off + ((size_t)b * npoint + s) * 3;
                o[0] = spx[far]; o[1] = spy[far]; o[2] = spz[far];
            }
        }
        float cx = spx[far], cy = spy[far], cz = spz[far];

        float bestd = -1.f; uint32_t besti = 0x7fffffffu;
#pragma unroll
        for (int t = 0; t < PT; t++) {
            int gi = tid + t * BDIM;
            if (gi < n) {
                float dx = px[t] - cx, dy = py[t] - cy, dz = pz[t] - cz;
                float d = dx * dx + dy * dy + dz * dz;
                if (d < dist[t]) dist[t] = d;
                if (dist[t] > bestd) { bestd = dist[t]; besti = gi; }
            }
        }
        uint32_t db = (bestd < 0.f) ? 0u : __float_as_uint(bestd);
        uint32_t wmax = redux_max(db);
        uint32_t wi = redux_min((db == wmax) ? besti : 0x7fffffffu);

        int par = (s & 1) * 32;
        if (lane == 0) { sd[par + wid] = wmax; si[par + wid] = wi; }
        __syncthreads();
        uint32_t dd = (lane < NW) ? sd[par + lane] : 0u;
        uint32_t ii = (lane < NW) ? si[par + lane] : 0x7fffffffu;
        uint32_t m2 = redux_max(dd);
        far = (int)redux_min((dd == m2) ? ii : 0x7fffffffu);
    }
}

// ---------------------------------------------------------------------------
// Fused layer-1: h1 = relu([conf,x]@w1 + b1) at FPS-1 points; fp16 out
// ---------------------------------------------------------------------------
__global__ void layer1_kernel(const float* __restrict__ x, const float* __restrict__ conf,
                              const float* __restrict__ w1, const float* __restrict__ b1)
{
    int gid = blockIdx.x * blockDim.x + threadIdx.x;
    if (gid >= M1 * 16) return;
    int r = gid >> 4, q = (gid & 15) * 4;
    int b = r / S1;
    int idx = g_idx[IDX1 + r];
    size_t pbase = (size_t)b * NPTS + idx;
    float a0 = conf[pbase];
    float a1 = x[pbase * 3], a2 = x[pbase * 3 + 1], a3 = x[pbase * 3 + 2];
    float o[4];
#pragma unroll
    for (int j = 0; j < 4; j++) {
        float v = b1[q + j];
        v += a0 * __ldg(&w1[0 * 64 + q + j]);
        v += a1 * __ldg(&w1[1 * 64 + q + j]);
        v += a2 * __ldg(&w1[2 * 64 + q + j]);
        v += a3 * __ldg(&w1[3 * 64 + q + j]);
        o[j] = fmaxf(v, 0.f);
    }
    __half2 p0 = __floats2half2_rn(o[0], o[1]);
    __half2 p1 = __floats2half2_rn(o[2], o[3]);
    uint2 pk = make_uint2(*(uint32_t*)&p0, *(uint32_t*)&p1);
    *(uint2*)(g_hbuf + HOFF_H1 + (size_t)r * 64 + q) = pk;
}

// ---------------------------------------------------------------------------
// fp16 HMMA GEMM, 3-stage cp.async pipeline, ldmatrix fragments, optional
// row-gather on A (idx_off >= 0: src row = (r/Sdst)*Ssrc + g_idx[idx_off+r]).
// flags: bit0 = relu, bit1 = half out (g_hbuf) else fp32 (g_scratch).
// ---------------------------------------------------------------------------
constexpr int LDW = 20;                       // words per smem row (16 + pad)
constexpr int TILE_W = 128 * LDW;
constexpr int TILE_B = TILE_W * 4;            // 10240 bytes
constexpr int TG_SMEM = 6 * TILE_B;           // 61440 bytes (3 stages x A,B)

__global__ void __launch_bounds__(256)
tgemm_kernel(long long hoffA, int lda, long long hoffW, const float* __restrict__ bias,
             long long offC, int ldc, int M, int N, int Kpad, int flags,
             int idx_off, int Sdst, int Ssrc)
{
    extern __shared__ uint32_t sm[];
    const __half* Wh = g_hbuf + hoffW;

    int tid = threadIdx.x, lane = tid & 31, wid = tid >> 5;
    int m0 = blockIdx.x * 128, n0 = blockIdx.y * 128;
    int wm = (wid >> 1) * 32, wn = (wid & 1) * 64;
    int g = lane >> 2, tg = lane & 3;

    float acc[2][8][4];
#pragma unroll
    for (int i = 0; i < 2; i++)
#pragma unroll
        for (int j = 0; j < 8; j++)
#pragma unroll
            for (int q = 0; q < 4; q++) acc[i][j][q] = 0.f;

    uint32_t sbase = smem_u32(sm);
    int nch = Kpad >> 5;

    int row0 = tid >> 2, cw = tid & 3;
    const __half* aptr[2];
    const __half* bptr[2];
    uint32_t soff[2];
#pragma unroll
    for (int j = 0; j < 2; j++) {
        int rloc = row0 + 64 * j;
        int rg = m0 + rloc;
        if (rg > M - 1) rg = M - 1;
        size_t srow;
        if (idx_off >= 0) {
            int bb = rg / Sdst;
            srow = (size_t)bb * Ssrc + g_idx[idx_off + rg];
        } else {
            srow = rg;
        }
        aptr[j] = g_hbuf + hoffA + srow * lda + cw * 8;
        bptr[j] = Wh + (size_t)(n0 + rloc) * Kpad + cw * 8;
        soff[j] = (rloc * LDW + cw * 4) << 2;
    }

#define TG_ISSUE(c)                                                   \
    do {                                                              \
        if ((c) < nch) {                                              \
            uint32_t aw = sbase + ((c) % 3) * 2 * TILE_B;             \
            uint32_t bw = aw + TILE_B;                                \
            int k0h = (c) * 32;                                       \
            _Pragma("unroll")                                         \
            for (int j = 0; j < 2; j++) {                             \
                cpa16(aw + soff[j], aptr[j] + k0h);                   \
                cpa16(bw + soff[j], bptr[j] + k0h);                   \
            }                                                         \
        }                                                             \
        cpa_commit();                                                 \
    } while (0)

    TG_ISSUE(0);
    TG_ISSUE(1);
    TG_ISSUE(2);

    uint32_t aoff = (((wm + (lane & 15)) * LDW + ((lane >> 4) << 2)) << 2);
    uint32_t boff = (((wn + ((lane >> 4)) * 8 + (lane & 7)) * LDW +
                      (((lane >> 3) & 1) << 2)) << 2);

    for (int c = 0; c < nch; c++) {
        cpa_wait2();
        __syncthreads();
        uint32_t Ab = sbase + (c % 3) * 2 * TILE_B;
        uint32_t Bb = Ab + TILE_B;
#pragma unroll
        for (int ks = 0; ks < 2; ks++) {
            uint32_t af[2][4];
#pragma unroll
            for (int mt = 0; mt < 2; mt++)
                ldsm4(af[mt][0], af[mt][1], af[mt][2], af[mt][3],
                      Ab + aoff + mt * 16 * LDW * 4 + ks * 32);
            uint32_t bf[8][2];
#pragma unroll
            for (int np = 0; np < 4; np++)
                ldsm4(bf[2 * np][0], bf[2 * np][1], bf[2 * np + 1][0], bf[2 * np + 1][1],
                      Bb + boff + np * 16 * LDW * 4 + ks * 32);
#pragma unroll
            for (int mt = 0; mt < 2; mt++)
#pragma unroll
                for (int nt = 0; nt < 8; nt++)
                    mma16n8k16(acc[mt][nt], af[mt], bf[nt]);
        }
        __syncthreads();
        TG_ISSUE(c + 3);
    }
#undef TG_ISSUE

    bool do_relu = flags & 1, half_out = flags & 2;
    __half* Ch = g_hbuf + offC;
    float*  Cf = g_scratch + offC;
#pragma unroll
    for (int mt = 0; mt < 2; mt++) {
        int r0 = m0 + wm + mt * 16 + g;
#pragma unroll
        for (int nt = 0; nt < 8; nt++) {
            int col = n0 + wn + nt * 8 + 2 * tg;
            float bz0 = bias[col], bz1 = bias[col + 1];
            float v0 = acc[mt][nt][0] + bz0, v1 = acc[mt][nt][1] + bz1;
            float v2 = acc[mt][nt][2] + bz0, v3 = acc[mt][nt][3] + bz1;
            if (do_relu) {
                v0 = fmaxf(v0, 0.f); v1 = fmaxf(v1, 0.f);
                v2 = fmaxf(v2, 0.f); v3 = fmaxf(v3, 0.f);
            }
            if (half_out) {
                __half2 pa = __floats2half2_rn(v0, v1);
                __half2 pb = __floats2half2_rn(v2, v3);
                if (r0 < M)     *(__half2*)(Ch + (size_t)r0 * ldc + col) = pa;
                if (r0 + 8 < M) *(__half2*)(Ch + (size_t)(r0 + 8) * ldc + col) = pb;
            } else {
                if (r0 < M) {
                    Cf[(size_t)r0 * ldc + col] = v0;
                    Cf[(size_t)r0 * ldc + col + 1] = v1;
                }
                if (r0 + 8 < M) {
                    Cf[(size_t)(r0 + 8) * ldc + col] = v2;
                    Cf[(size_t)(r0 + 8) * ldc + col + 1] = v3;
                }
            }
        }
    }
}

// ---------------------------------------------------------------------------
// Copy sampled xyz into trailing 3 cols of a half concat buffer
// ---------------------------------------------------------------------------
__global__ void copy3_kernel(long long src_off, long long dst_hoff, int ldd, int rows)
{
    int r = blockIdx.x * blockDim.x + threadIdx.x;
    if (r >= rows) return;
    const float* s = g_scratch + src_off + (size_t)r * 3;
    __half* d = g_hbuf + dst_hoff + (size_t)r * ldd;
    d[0] = __float2half_rn(s[0]);
    d[1] = __float2half_rn(s[1]);
    d[2] = __float2half_rn(s[2]);
}

// ---------------------------------------------------------------------------
// Max-pool l8 (fp32) over 125 sampled points per batch
// ---------------------------------------------------------------------------
__global__ void maxpool_kernel(float* __restrict__ out)
{
    int e = blockIdx.x * blockDim.x + threadIdx.x;
    if (e >= BATCH * 512) return;
    int b = e >> 9, c = e & 511;
    const float* base = g_scratch + OFF_L8 + (size_t)b * S3 * 512 + c;
    float m = base[0];
    for (int s = 1; s < S3; s++) m = fmaxf(m, base[(size_t)s * 512]);
    out[e] = m;
}

// ---------------------------------------------------------------------------
// Launch: FPS chain on a side stream (fork/join via events, graph-capturable)
// ---------------------------------------------------------------------------
extern "C" void kernel_launch(void* const* d_in, const int* in_sizes, int n_in,
                              void* d_out, int out_size)
{
    const float* x    = (const float*)d_in[0];
    const float* cw1  = (const float*)d_in[1];
    const float* cb1  = (const float*)d_in[2];
    const float* cw2  = (const float*)d_in[3];
    const float* cb2  = (const float*)d_in[4];
    const float* w1   = (const float*)d_in[5];
    const float* b1   = (const float*)d_in[6];
    const float* w2   = (const float*)d_in[7];
    const float* b2   = (const float*)d_in[8];
    const float* w3   = (const float*)d_in[9];
    const float* b3   = (const float*)d_in[10];
    const float* w4   = (const float*)d_in[11];
    const float* b4   = (const float*)d_in[12];
    const float* w5   = (const float*)d_in[13];
    const float* b5   = (const float*)d_in[14];
    const float* w6   = (const float*)d_in[15];
    const float* b6   = (const float*)d_in[16];
    const float* pc1w = (const float*)d_in[17];
    const float* pc1b = (const float*)d_in[18];
    const float* pc2w = (const float*)d_in[19];
    const float* pc2b = (const float*)d_in[20];

    float* out  = (float*)d_out;            // (B,512)
    float* conf = out + BATCH * 512;        // (B,N,1)

    static cudaStream_t s1 = nullptr;
    static cudaEvent_t evFork, evF1, evF2, evF3;
    if (!s1) {
        cudaStreamCreateWithFlags(&s1, cudaStreamNonBlocking);
        cudaEventCreateWithFlags(&evFork, cudaEventDisableTiming);
        cudaEventCreateWithFlags(&evF1, cudaEventDisableTiming);
        cudaEventCreateWithFlags(&evF2, cudaEventDisableTiming);
        cudaEventCreateWithFlags(&evF3, cudaEventDisableTiming);
        cudaFuncSetAttribute(tgemm_kernel, cudaFuncAttributeMaxDynamicSharedMemorySize,
                             TG_SMEM);
        cudaFuncSetAttribute(fps_kernel<512, 8>,
                             cudaFuncAttributeMaxDynamicSharedMemorySize,
                             3 * NPTS * 4 + 1024);
    }

    cudaEventRecord(evFork, 0);
    cudaStreamWaitEvent(s1, evFork, 0);
    fps_kernel<512, 8><<<BATCH, 512, 3 * NPTS * 4 + 1024, s1>>>(
        x, -1LL, NPTS, S1, IDX1, (long long)OFF_NX1);
    cudaEventRecord(evF1, s1);
    fps_kernel<256, 2><<<BATCH, 256, 3 * S1 * 4 + 1024, s1>>>(
        nullptr, (long long)OFF_NX1, S1, S2, IDX2, (long long)OFF_NX2);
    cudaEventRecord(evF2, s1);
    fps_kernel<128, 2><<<BATCH, 128, 3 * S2 * 4 + 1024, s1>>>(
        nullptr, (long long)OFF_NX2, S2, S3, IDX3, -1LL);
    cudaEventRecord(evF3, s1);

    wconv_kernel<<<(WC_TOTAL + 255) / 256, 256>>>(w2, pc1w, w3, w4, pc2w, w5, w6);
    conf_kernel<<<(BATCH * NPTS + 255) / 256, 256>>>(x, cw1, cb1, cw2, cb2, conf);

    cudaStreamWaitEvent(0, evF1, 0);
    layer1_kernel<<<(M1 * 16 + 255) / 256, 256>>>(x, conf, w1, b1);

    // h1 @ w2 -> l2g
    tgemm_kernel<<<dim3(M1 / 128, 2), 256, TG_SMEM>>>(
        (long long)HOFF_H1, 64, (long long)(HOFF_WC + WC_W2), b2,
        (long long)HOFF_L2G, 256, M1, 256, 64, 3, -1, 0, 0);
    // l2g @ pc1w -> cat1[:,0:256]
    tgemm_kernel<<<dim3(M1 / 128, 2), 256, TG_SMEM>>>(
        (long long)HOFF_L2G, 256, (long long)(HOFF_WC + WC_PC1), pc1b,
        (long long)HOFF_CAT1, 264, M1, 256, 256, 2, -1, 0, 0);
    copy3_kernel<<<(M1 + 255) / 256, 256>>>((long long)OFF_NX1,
                                            (long long)(HOFF_CAT1 + 256), 264, M1);
    // cat1 @ w3p -> l4
    tgemm_kernel<<<dim3(M1 / 128, 2), 256, TG_SMEM>>>(
        (long long)HOFF_CAT1, 264, (long long)(HOFF_WC + WC_W3), b3,
        (long long)HOFF_L4, 256, M1, 256, 288, 3, -1, 0, 0);
    // l4 @ w4 -> l5
    tgemm_kernel<<<dim3(M1 / 128, 3), 256, TG_SMEM>>>(
        (long long)HOFF_L4, 256, (long long)(HOFF_WC + WC_W4), b4,
        (long long)HOFF_L5, 384, M1, 384, 256, 3, -1, 0, 0);

    cudaStreamWaitEvent(0, evF2, 0);
    // gather(l5, idx2) @ pc2w -> cat2[:,0:384]
    tgemm_kernel<<<dim3(M2 / 128, 3), 256, TG_SMEM>>>(
        (long long)HOFF_L5, 384, (long long)(HOFF_WC + WC_PC2), pc2b,
        (long long)HOFF_CAT2, 392, M2, 384, 384, 2, IDX2, S2, S1);
    copy3_kernel<<<(M2 + 255) / 256, 256>>>((long long)OFF_NX2,
                                            (long long)(HOFF_CAT2 + 384), 392, M2);
    // cat2 @ w5p -> l7
    tgemm_kernel<<<dim3(M2 / 128, 3), 256, TG_SMEM>>>(
        (long long)HOFF_CAT2, 392, (long long)(HOFF_WC + WC_W5), b5,
        (long long)HOFF_L7, 384, M2, 384, 416, 3, -1, 0, 0);

    cudaStreamWaitEvent(0, evF3, 0);
    // gather(l7, idx3) @ w6 -> l8 (fp32)
    tgemm_kernel<<<dim3((M3 + 127) / 128, 4), 256, TG_SMEM>>>(
        (long long)HOFF_L7, 384, (long long)(HOFF_WC + WC_W6), b6,
        (long long)OFF_L8, 512, M3, 512, 384, 1, IDX3, S3, S2);
    maxpool_kernel<<<(BATCH * 512 + 255) / 256, 256>>>(out);
}